// round 5
// baseline (speedup 1.0000x reference)
#include <cuda_runtime.h>
#include <cuda_bf16.h>
#include <math.h>

// Problem constants
#define BB 256      // batch
#define TT 512      // seq len
#define SS 64       // state dim
#define OO 128      // obs dim
#define HH 128      // LSTM hidden
#define GG 512      // 4*H

// ---------------- scratch (static __device__ — no allocation) ----------------
__device__ float g_pm   [(size_t)BB * TT * SS];   // prior mean
__device__ float g_logsq[(size_t)BB * TT * SS];   // log(prior_scale)
__device__ float g_i2s2 [(size_t)BB * TT * SS];   // 0.5 / prior_scale^2
__device__ float g_X    [(size_t)BB * TT * GG];   // obs @ K_lstm + b_lstm
__device__ float g_hs   [(size_t)BB * TT * HH];   // LSTM hidden states
#define LOSS_BLOCKS 2048
__device__ float g_part [LOSS_BLOCKS * 2];

// ---------------- helpers ----------------
__device__ __forceinline__ float softplusf(float x) {
    // stable log1p(exp(x))
    return (x > 0.f) ? (x + log1pf(expf(-x))) : log1pf(expf(x));
}
__device__ __forceinline__ float sigmoidf_(float x) {
    return 1.f / (1.f + expf(-x));
}

// ============================================================================
// 1) Prior rollout: m_t = m_{t-1} @ Wf_m + bf_m ; s_t = softplus(m_{t-1} @ Wf_s + bf_s)
//    One block per batch row, 64 threads (one per state column).
// ============================================================================
__global__ __launch_bounds__(64) void prior_kernel(
    const float* __restrict__ im, const float* __restrict__ Wfm,
    const float* __restrict__ bfm, const float* __restrict__ Wfs,
    const float* __restrict__ bfs)
{
    __shared__ float sWm[SS * SS];
    __shared__ float sWs[SS * SS];
    __shared__ float m[2][SS];

    const int j = threadIdx.x;
    const int b = blockIdx.x;

    for (int idx = j; idx < SS * SS; idx += 64) {
        sWm[idx] = Wfm[idx];
        sWs[idx] = Wfs[idx];
    }
    const float bm = bfm[j];
    const float bs = bfs[j];
    m[0][j] = im[b * SS + j];
    __syncthreads();

    float* __restrict__ pmb = g_pm    + (size_t)b * TT * SS;
    float* __restrict__ lqb = g_logsq + (size_t)b * TT * SS;
    float* __restrict__ isb = g_i2s2  + (size_t)b * TT * SS;

    int cur = 0;
    for (int t = 0; t < TT; t++) {
        float am0 = bm, am1 = 0.f, as0 = bs, as1 = 0.f;
        #pragma unroll 8
        for (int i = 0; i < SS; i += 2) {
            float mi0 = m[cur][i];
            float mi1 = m[cur][i + 1];
            am0 = fmaf(mi0, sWm[i * SS + j], am0);
            am1 = fmaf(mi1, sWm[(i + 1) * SS + j], am1);
            as0 = fmaf(mi0, sWs[i * SS + j], as0);
            as1 = fmaf(mi1, sWs[(i + 1) * SS + j], as1);
        }
        float am = am0 + am1;
        float sp = softplusf(as0 + as1);

        pmb[t * SS + j] = am;
        lqb[t * SS + j] = logf(sp);
        isb[t * SS + j] = 0.5f / (sp * sp);

        m[cur ^ 1][j] = am;
        __syncthreads();
        cur ^= 1;
    }
}

// ============================================================================
// 2) X = obs @ K_lstm + b_lstm : [131072 x 128] @ [128 x 512]
//    Classic fp32 SGEMM: 128x128 block tile, 8x8 thread tile, BK=16, double buffer.
// ============================================================================
#define XBM 128
#define XBN 128
#define XBK 16
__global__ __launch_bounds__(256) void xgemm_kernel(
    const float* __restrict__ A,      // [M,128] (obs)
    const float* __restrict__ Bmat,   // [128,512] (K_lstm)
    const float* __restrict__ bias)   // [512]
{
    __shared__ float As[2][XBK][XBM];
    __shared__ float Bs[2][XBK][XBN];

    const int tid = threadIdx.x;
    const int M0 = blockIdx.x * XBM;
    const int N0 = blockIdx.y * XBN;

    // loader indices
    const int a_r = tid >> 2;              // 0..63
    const int a_c = (tid & 3) << 2;        // 0,4,8,12  (k-offset)
    const int b_r = tid >> 5;              // 0..7      (k row)
    const int b_c = (tid & 31) << 2;       // 0..124    (n offset)

    // compute indices
    const int tm8 = (tid >> 4) << 3;       // 0..120
    const int tn8 = (tid & 15) << 3;       // 0..120

    const float* Arow0 = A + (size_t)(M0 + a_r) * OO;
    const float* Arow1 = A + (size_t)(M0 + a_r + 64) * OO;

    // preload k-tile 0
    {
        float4 pa0 = *(const float4*)(Arow0 + a_c);
        float4 pa1 = *(const float4*)(Arow1 + a_c);
        float4 pb0 = *(const float4*)(Bmat + (size_t)b_r * GG + N0 + b_c);
        float4 pb1 = *(const float4*)(Bmat + (size_t)(b_r + 8) * GG + N0 + b_c);
        As[0][a_c + 0][a_r] = pa0.x; As[0][a_c + 1][a_r] = pa0.y;
        As[0][a_c + 2][a_r] = pa0.z; As[0][a_c + 3][a_r] = pa0.w;
        As[0][a_c + 0][a_r + 64] = pa1.x; As[0][a_c + 1][a_r + 64] = pa1.y;
        As[0][a_c + 2][a_r + 64] = pa1.z; As[0][a_c + 3][a_r + 64] = pa1.w;
        *(float4*)&Bs[0][b_r][b_c]     = pb0;
        *(float4*)&Bs[0][b_r + 8][b_c] = pb1;
    }
    __syncthreads();

    float acc[8][8];
    #pragma unroll
    for (int i = 0; i < 8; i++)
        #pragma unroll
        for (int jj = 0; jj < 8; jj++) acc[i][jj] = 0.f;

    #pragma unroll
    for (int kt = 0; kt < 8; kt++) {
        const int buf = kt & 1;
        float4 pa0, pa1, pb0, pb1;
        if (kt < 7) {
            const int k0 = (kt + 1) * XBK;
            pa0 = *(const float4*)(Arow0 + k0 + a_c);
            pa1 = *(const float4*)(Arow1 + k0 + a_c);
            pb0 = *(const float4*)(Bmat + (size_t)(k0 + b_r) * GG + N0 + b_c);
            pb1 = *(const float4*)(Bmat + (size_t)(k0 + b_r + 8) * GG + N0 + b_c);
        }
        #pragma unroll
        for (int k = 0; k < XBK; k++) {
            float4 a0 = *(const float4*)&As[buf][k][tm8];
            float4 a1 = *(const float4*)&As[buf][k][tm8 + 4];
            float4 b0 = *(const float4*)&Bs[buf][k][tn8];
            float4 b1 = *(const float4*)&Bs[buf][k][tn8 + 4];
            float av[8] = {a0.x, a0.y, a0.z, a0.w, a1.x, a1.y, a1.z, a1.w};
            float bv[8] = {b0.x, b0.y, b0.z, b0.w, b1.x, b1.y, b1.z, b1.w};
            #pragma unroll
            for (int i = 0; i < 8; i++)
                #pragma unroll
                for (int jj = 0; jj < 8; jj++)
                    acc[i][jj] = fmaf(av[i], bv[jj], acc[i][jj]);
        }
        if (kt < 7) {
            const int nb = buf ^ 1;
            As[nb][a_c + 0][a_r] = pa0.x; As[nb][a_c + 1][a_r] = pa0.y;
            As[nb][a_c + 2][a_r] = pa0.z; As[nb][a_c + 3][a_r] = pa0.w;
            As[nb][a_c + 0][a_r + 64] = pa1.x; As[nb][a_c + 1][a_r + 64] = pa1.y;
            As[nb][a_c + 2][a_r + 64] = pa1.z; As[nb][a_c + 3][a_r + 64] = pa1.w;
            *(float4*)&Bs[nb][b_r][b_c]     = pb0;
            *(float4*)&Bs[nb][b_r + 8][b_c] = pb1;
            __syncthreads();
        }
    }

    // epilogue: add bias, store
    float4 bs0 = *(const float4*)(bias + N0 + tn8);
    float4 bs1 = *(const float4*)(bias + N0 + tn8 + 4);
    #pragma unroll
    for (int i = 0; i < 8; i++) {
        float4 o0, o1;
        o0.x = acc[i][0] + bs0.x; o0.y = acc[i][1] + bs0.y;
        o0.z = acc[i][2] + bs0.z; o0.w = acc[i][3] + bs0.w;
        o1.x = acc[i][4] + bs1.x; o1.y = acc[i][5] + bs1.y;
        o1.z = acc[i][6] + bs1.z; o1.w = acc[i][7] + bs1.w;
        float* Crow = g_X + (size_t)(M0 + tm8 + i) * GG + N0 + tn8;
        *(float4*)(Crow)     = o0;
        *(float4*)(Crow + 4) = o1;
    }
}

// ============================================================================
// 3) LSTM recurrence. 128 blocks x 512 threads; block handles 2 batch rows.
//    R resident in smem as bf16x2 (row pairs packed), unpacked to fp32 in regs.
//    Thread j owns gate column j for both rows. 256 gate threads own (row,k) state.
// ============================================================================
__global__ __launch_bounds__(512, 1) void lstm_kernel(const float* __restrict__ R)
{
    extern __shared__ unsigned char sm_raw[];
    unsigned* R2   = (unsigned*)sm_raw;                       // 64*512 words = 128KB
    float*    hbuf = (float*)(sm_raw + 131072);               // 2 bufs * 64 pairs * 4 = 512 f
    float*    zbuf = (float*)(sm_raw + 131072 + 2048);        // 2 * 512 f

    const int j   = threadIdx.x;          // 0..511
    const int r0  = blockIdx.x * 2;

    // pack R into bf16x2 (rows 2p, 2p+1 of column j)
    #pragma unroll 4
    for (int p = 0; p < 64; p++) {
        float rv0 = R[(size_t)(2 * p) * GG + j];
        float rv1 = R[(size_t)(2 * p + 1) * GG + j];
        unsigned lo = (unsigned)__bfloat16_as_ushort(__float2bfloat16(rv0));
        unsigned hi = (unsigned)__bfloat16_as_ushort(__float2bfloat16(rv1));
        R2[p * 512 + j] = (hi << 16) | lo;
    }
    // zero h buffers
    hbuf[j] = 0.f;
    __syncthreads();

    const float* __restrict__ px0 = g_X + (size_t)r0 * TT * GG + j;
    const float* __restrict__ px1 = g_X + (size_t)(r0 + 1) * TT * GG + j;
    float xc0 = px0[0];
    float xc1 = px1[0];

    // gate-state ownership
    const int grow = j >> 7;            // valid for j<256
    const int gk   = j & 127;
    float c = 0.f;

    int cur = 0;
    for (int t = 0; t < TT; t++) {
        float a0a = xc0, a0b = 0.f, a1a = xc1, a1b = 0.f;
        if (t + 1 < TT) {
            xc0 = px0[(size_t)(t + 1) * GG];
            xc1 = px1[(size_t)(t + 1) * GG];
        }
        const unsigned* __restrict__ Rcol = R2 + j;
        const float4*   __restrict__ hb   = (const float4*)(hbuf + cur * 256);
        #pragma unroll 16
        for (int p = 0; p < 64; p++) {
            unsigned w = Rcol[p * 512];
            float4 hv = hb[p];
            float f0 = __uint_as_float(w << 16);
            float f1 = __uint_as_float(w & 0xffff0000u);
            a0a = fmaf(hv.x, f0, a0a);
            a0b = fmaf(hv.y, f1, a0b);
            a1a = fmaf(hv.z, f0, a1a);
            a1b = fmaf(hv.w, f1, a1b);
        }
        zbuf[j]       = a0a + a0b;
        zbuf[512 + j] = a1a + a1b;
        __syncthreads();

        if (j < 256) {
            const float* zr = zbuf + grow * 512;
            float iz = zr[gk];
            float fz = zr[gk + 128];
            float gz = zr[gk + 256];
            float oz = zr[gk + 384];
            c = sigmoidf_(fz) * c + sigmoidf_(iz) * tanhf(gz);
            float h = sigmoidf_(oz) * tanhf(c);
            hbuf[(cur ^ 1) * 256 + (gk >> 1) * 4 + (gk & 1) + 2 * grow] = h;
            g_hs[((size_t)(r0 + grow) * TT + t) * HH + gk] = h;
        }
        __syncthreads();
        cur ^= 1;
    }
}

// ============================================================================
// 4) Heads + generator + loss, fused. 2048 blocks x 256 threads, 64 rows/block.
// ============================================================================
__global__ __launch_bounds__(256) void loss_kernel(
    const float* __restrict__ obs,
    const float* __restrict__ Wrm, const float* __restrict__ brm,
    const float* __restrict__ Wrs, const float* __restrict__ brs,
    const float* __restrict__ Wgm, const float* __restrict__ bgm,
    const float* __restrict__ Wgs, const float* __restrict__ bgs)
{
    extern __shared__ float sm[];
    float* sWrm = sm;                 // 128*64
    float* sWrs = sWrm + 8192;
    float* sWgm = sWrs + 8192;        // 64*128
    float* sWgs = sWgm + 8192;
    float* shs  = sWgs + 8192;        // 64*128
    float* spm  = shs + 8192;         // 64*64
    float* sred = spm + 4096;         // 512

    const int tid = threadIdx.x;
    const int m0  = blockIdx.x * 64;   // flattened (b*T+t) row base

    for (int idx = tid; idx < 8192; idx += 256) {
        sWrm[idx] = Wrm[idx];
        sWrs[idx] = Wrs[idx];
        sWgm[idx] = Wgm[idx];
        sWgs[idx] = Wgs[idx];
        shs[idx]  = g_hs[(size_t)m0 * HH + idx];
    }
    __syncthreads();

    float klp = 0.f, rec = 0.f;

    // ---- phase 1: posterior heads + KL ----
    {
        const int s = tid & 63;
        const int rbase = tid >> 6;                 // 0..3
        const float bm = brm[s];
        const float bsv = brs[s];
        #pragma unroll 1
        for (int it = 0; it < 16; it++) {
            const int r = rbase + (it << 2);
            const float* hrow = shs + r * HH;
            float am = bm, as = bsv;
            #pragma unroll 8
            for (int i = 0; i < HH; i++) {
                float h = hrow[i];
                am = fmaf(h, sWrm[i * 64 + s], am);
                as = fmaf(h, sWrs[i * 64 + s], as);
            }
            float sp = softplusf(as);
            size_t idx = (size_t)(m0 + r) * SS + s;
            float dm = am - g_pm[idx];
            klp += g_logsq[idx] - logf(sp)
                 + (sp * sp + dm * dm) * g_i2s2[idx] - 0.5f;
            spm[r * 64 + s] = am;
        }
    }
    __syncthreads();

    // ---- phase 2: generator + reconstruction ----
    {
        const int o = tid & 127;
        const int rbase = tid >> 7;                 // 0..1
        const float bm = bgm[o];
        const float bsv = bgs[o];
        #pragma unroll 1
        for (int it = 0; it < 32; it++) {
            const int r = rbase + (it << 1);
            const float* prow = spm + r * 64;
            float am = bm, as = bsv;
            #pragma unroll 8
            for (int s = 0; s < 64; s++) {
                float p = prow[s];
                am = fmaf(p, sWgm[s * 128 + o], am);
                as = fmaf(p, sWgs[s * 128 + o], as);
            }
            float os = softplusf(as);
            float ob = obs[(size_t)(m0 + r) * OO + o];
            float d = (ob - am) / os;
            rec += 0.5f * d * d + logf(os) + 0.91893853320467274f; // 0.5*log(2*pi)
        }
    }

    // ---- block reduction (deterministic tree) ----
    sred[tid]       = klp;
    sred[256 + tid] = rec;
    __syncthreads();
    #pragma unroll
    for (int st = 128; st > 0; st >>= 1) {
        if (tid < st) {
            sred[tid]       += sred[tid + st];
            sred[256 + tid] += sred[256 + tid + st];
        }
        __syncthreads();
    }
    if (tid == 0) {
        g_part[blockIdx.x * 2]     = sred[0];
        g_part[blockIdx.x * 2 + 1] = sred[256];
    }
}

// ============================================================================
// 5) Final deterministic reduce (double accumulation)
// ============================================================================
__global__ __launch_bounds__(256) void reduce_kernel(float* __restrict__ out)
{
    __shared__ double sk[256];
    __shared__ double sr[256];
    const int tid = threadIdx.x;
    double k = 0.0, r = 0.0;
    for (int i = tid; i < LOSS_BLOCKS; i += 256) {
        k += (double)g_part[2 * i];
        r += (double)g_part[2 * i + 1];
    }
    sk[tid] = k; sr[tid] = r;
    __syncthreads();
    #pragma unroll
    for (int st = 128; st > 0; st >>= 1) {
        if (tid < st) { sk[tid] += sk[tid + st]; sr[tid] += sr[tid + st]; }
        __syncthreads();
    }
    if (tid == 0)
        out[0] = (float)(sk[0] / ((double)BB * (double)TT) + sr[0] / (double)BB);
}

// ============================================================================
// launch
// ============================================================================
extern "C" void kernel_launch(void* const* d_in, const int* in_sizes, int n_in,
                              void* d_out, int out_size)
{
    const float* obs = (const float*)d_in[0];
    const float* im  = (const float*)d_in[1];
    // d_in[2] = initial_scale (unused by the reference forward)
    const float* Wfm = (const float*)d_in[3];
    const float* bfm = (const float*)d_in[4];
    const float* Wfs = (const float*)d_in[5];
    const float* bfs = (const float*)d_in[6];
    const float* Wgm = (const float*)d_in[7];
    const float* bgm = (const float*)d_in[8];
    const float* Wgs = (const float*)d_in[9];
    const float* bgs = (const float*)d_in[10];
    const float* K   = (const float*)d_in[11];
    const float* R   = (const float*)d_in[12];
    const float* bl  = (const float*)d_in[13];
    const float* Wrm = (const float*)d_in[14];
    const float* brm = (const float*)d_in[15];
    const float* Wrs = (const float*)d_in[16];
    const float* brs = (const float*)d_in[17];

    const int LSTM_SMEM = 131072 + 2048 + 4096;          // 137216 B
    const int LOSS_SMEM = (8192 * 5 + 4096 + 512) * 4;   // 182272 B
    cudaFuncSetAttribute(lstm_kernel, cudaFuncAttributeMaxDynamicSharedMemorySize, LSTM_SMEM);
    cudaFuncSetAttribute(loss_kernel, cudaFuncAttributeMaxDynamicSharedMemorySize, LOSS_SMEM);

    prior_kernel<<<BB, 64>>>(im, Wfm, bfm, Wfs, bfs);
    xgemm_kernel<<<dim3((BB * TT) / XBM, GG / XBN), 256>>>(obs, K, bl);
    lstm_kernel<<<BB / 2, 512, LSTM_SMEM>>>(R);
    loss_kernel<<<LOSS_BLOCKS, 256, LOSS_SMEM>>>(obs, Wrm, brm, Wrs, brs,
                                                 Wgm, bgm, Wgs, bgs);
    reduce_kernel<<<1, 256>>>((float*)d_out);
}

// round 10
// speedup vs baseline: 1.1322x; 1.1322x over previous
#include <cuda_runtime.h>
#include <cuda_bf16.h>
#include <math.h>
#include <stdint.h>

// Problem constants
#define BB 256      // batch
#define TT 512      // seq len
#define SS 64       // state dim
#define OO 128      // obs dim
#define HH 128      // LSTM hidden
#define GG 512      // 4*H
#define MT (BB*TT)  // 131072 flattened rows

// ---------------- scratch (static __device__ — no allocation) ----------------
__device__ float g_pm   [(size_t)BB * TT * SS];   // prior mean
__device__ float g_logsq[(size_t)BB * TT * SS];   // log(prior_scale)
__device__ float g_i2s2 [(size_t)BB * TT * SS];   // 0.5 / prior_scale^2
__device__ float g_X    [(size_t)BB * TT * GG];   // obs @ K_lstm + b_lstm
__device__ float g_hs   [(size_t)BB * TT * HH];   // LSTM hidden states
__device__ __nv_bfloat16 g_Abf[(size_t)MT * OO];  // obs in bf16
__device__ __nv_bfloat16 g_Kt [(size_t)GG * OO];  // K_lstm transposed [N,K] bf16
#define LOSS_BLOCKS 2048
__device__ float g_part [LOSS_BLOCKS * 2];

// ---------------- helpers ----------------
__device__ __forceinline__ uint32_t smem_u32(const void* p) {
    uint32_t a;
    asm("{ .reg .u64 t; cvta.to.shared.u64 t, %1; cvt.u32.u64 %0, t; }" : "=r"(a) : "l"(p));
    return a;
}
__device__ __forceinline__ float softplusf(float x) {
    return (x > 0.f) ? (x + log1pf(expf(-x))) : log1pf(expf(x));
}
__device__ __forceinline__ float sigmoidf_(float x) {
    return 1.f / (1.f + expf(-x));
}

// ============================================================================
// 0a) Convert obs -> bf16
// ============================================================================
__global__ __launch_bounds__(256) void conv_kernel(const float* __restrict__ obs)
{
    size_t i = (size_t)blockIdx.x * 256 + threadIdx.x;   // over MT*OO/4
    float4 v = ((const float4*)obs)[i];
    __nv_bfloat162* dst = (__nv_bfloat162*)g_Abf;
    dst[2 * i]     = __floats2bfloat162_rn(v.x, v.y);
    dst[2 * i + 1] = __floats2bfloat162_rn(v.z, v.w);
}

// 0b) Transpose K_lstm [128,512] -> g_Kt [512,128] bf16
__global__ __launch_bounds__(128) void kt_kernel(const float* __restrict__ K)
{
    int n = blockIdx.x;           // 0..511
    int k = threadIdx.x;          // 0..127
    g_Kt[(size_t)n * OO + k] = __float2bfloat16(K[(size_t)k * GG + n]);
}

// ============================================================================
// 1) Prior rollout (unchanged — passing R4 version)
// ============================================================================
__global__ __launch_bounds__(64) void prior_kernel(
    const float* __restrict__ im, const float* __restrict__ Wfm,
    const float* __restrict__ bfm, const float* __restrict__ Wfs,
    const float* __restrict__ bfs)
{
    __shared__ float sWm[SS * SS];
    __shared__ float sWs[SS * SS];
    __shared__ float m[2][SS];

    const int j = threadIdx.x;
    const int b = blockIdx.x;

    for (int idx = j; idx < SS * SS; idx += 64) {
        sWm[idx] = Wfm[idx];
        sWs[idx] = Wfs[idx];
    }
    const float bm = bfm[j];
    const float bs = bfs[j];
    m[0][j] = im[b * SS + j];
    __syncthreads();

    float* __restrict__ pmb = g_pm    + (size_t)b * TT * SS;
    float* __restrict__ lqb = g_logsq + (size_t)b * TT * SS;
    float* __restrict__ isb = g_i2s2  + (size_t)b * TT * SS;

    int cur = 0;
    for (int t = 0; t < TT; t++) {
        float am0 = bm, am1 = 0.f, as0 = bs, as1 = 0.f;
        #pragma unroll 8
        for (int i = 0; i < SS; i += 2) {
            float mi0 = m[cur][i];
            float mi1 = m[cur][i + 1];
            am0 = fmaf(mi0, sWm[i * SS + j], am0);
            am1 = fmaf(mi1, sWm[(i + 1) * SS + j], am1);
            as0 = fmaf(mi0, sWs[i * SS + j], as0);
            as1 = fmaf(mi1, sWs[(i + 1) * SS + j], as1);
        }
        float am = am0 + am1;
        float sp = softplusf(as0 + as1);

        pmb[t * SS + j] = am;
        lqb[t * SS + j] = logf(sp);
        isb[t * SS + j] = 0.5f / (sp * sp);

        m[cur ^ 1][j] = am;
        __syncthreads();
        cur ^= 1;
    }
}

// ============================================================================
// 2) X = obs @ K_lstm + b_lstm via mma.sync bf16 (HMMA — baseline PTX, no 'a')
//    Block tile 128M x 128N, K=128 whole. 8 warps (4M x 2N), warp tile 32x64.
//    ldmatrix from padded smem (stride 136 elems -> conflict-free).
// ============================================================================
#define XSTR 136   // padded smem row stride in bf16 elems (272B = 68 words, +4 banks/row)
#define XSM_A 0
#define XSM_B (128 * XSTR * 2)
#define XSM_BIAS (2 * 128 * XSTR * 2)
#define XSM_TOT (XSM_BIAS + 128 * 4)       // 70144 bytes

__global__ __launch_bounds__(256, 2) void xgemm_mma(const float* __restrict__ bias)
{
    extern __shared__ unsigned char smraw[];
    __nv_bfloat16* sA = (__nv_bfloat16*)(smraw + XSM_A);
    __nv_bfloat16* sB = (__nv_bfloat16*)(smraw + XSM_B);
    float* sbias = (float*)(smraw + XSM_BIAS);

    const int tid  = threadIdx.x;
    const int lane = tid & 31;
    const int wid  = tid >> 5;
    const int m0 = blockIdx.x * 128;
    const int n0 = blockIdx.y * 128;

    // ---- stage A[128x128] and B[128x128] bf16 tiles ----
    {
        const int r  = tid >> 4;          // 0..15
        const int cc = (tid & 15) * 8;    // k offset (uint4 = 8 bf16)
        #pragma unroll
        for (int i = 0; i < 8; i++) {
            int row = r + i * 16;
            uint4 va = *(const uint4*)(g_Abf + (size_t)(m0 + row) * OO + cc);
            *(uint4*)(sA + row * XSTR + cc) = va;
            uint4 vb = *(const uint4*)(g_Kt + (size_t)(n0 + row) * OO + cc);
            *(uint4*)(sB + row * XSTR + cc) = vb;
        }
    }
    if (tid < 128) sbias[tid] = bias[n0 + tid];
    __syncthreads();

    const int wm = (wid & 3) * 32;        // warp M offset in tile
    const int wn = (wid >> 2) * 64;       // warp N offset in tile
    const uint32_t sA_u = smem_u32(sA);
    const uint32_t sB_u = smem_u32(sB);

    float acc[2][8][4];
    #pragma unroll
    for (int im = 0; im < 2; im++)
        #pragma unroll
        for (int j = 0; j < 8; j++)
            #pragma unroll
            for (int c = 0; c < 4; c++) acc[im][j][c] = 0.f;

    const int q  = lane >> 3;   // quad 0..3 (ldmatrix address group)
    const int r8 = lane & 7;

    #pragma unroll
    for (int kk = 0; kk < 8; kk++) {
        const int k0 = kk * 16;

        // A fragments: 2 m16k16 tiles
        uint32_t ra[2][4];
        #pragma unroll
        for (int im = 0; im < 2; im++) {
            int row = wm + im * 16 + (q & 1) * 8 + r8;
            int col = k0 + (q >> 1) * 8;
            uint32_t addr = sA_u + (uint32_t)((row * XSTR + col) * 2);
            asm volatile(
                "ldmatrix.sync.aligned.m8n8.x4.shared.b16 {%0,%1,%2,%3}, [%4];"
                : "=r"(ra[im][0]), "=r"(ra[im][1]), "=r"(ra[im][2]), "=r"(ra[im][3])
                : "r"(addr));
        }
        // B fragments: 8 n8k16 tiles, loaded 2 per ldmatrix.x4
        uint32_t rb[8][2];
        #pragma unroll
        for (int jn = 0; jn < 4; jn++) {
            int row = wn + jn * 16 + (q >> 1) * 8 + r8;
            int col = k0 + (q & 1) * 8;
            uint32_t addr = sB_u + (uint32_t)((row * XSTR + col) * 2);
            asm volatile(
                "ldmatrix.sync.aligned.m8n8.x4.shared.b16 {%0,%1,%2,%3}, [%4];"
                : "=r"(rb[2 * jn][0]), "=r"(rb[2 * jn][1]),
                  "=r"(rb[2 * jn + 1][0]), "=r"(rb[2 * jn + 1][1])
                : "r"(addr));
        }
        #pragma unroll
        for (int im = 0; im < 2; im++)
            #pragma unroll
            for (int j = 0; j < 8; j++) {
                asm volatile(
                    "mma.sync.aligned.m16n8k16.row.col.f32.bf16.bf16.f32 "
                    "{%0,%1,%2,%3}, {%4,%5,%6,%7}, {%8,%9}, {%0,%1,%2,%3};"
                    : "+f"(acc[im][j][0]), "+f"(acc[im][j][1]),
                      "+f"(acc[im][j][2]), "+f"(acc[im][j][3])
                    : "r"(ra[im][0]), "r"(ra[im][1]), "r"(ra[im][2]), "r"(ra[im][3]),
                      "r"(rb[j][0]), "r"(rb[j][1]));
            }
    }

    // ---- epilogue: bias + fp32 store ----
    const int g  = lane >> 2;
    const int t2 = (lane & 3) * 2;
    #pragma unroll
    for (int im = 0; im < 2; im++) {
        #pragma unroll
        for (int j = 0; j < 8; j++) {
            const int col = wn + j * 8 + t2;
            const float bx = sbias[col];
            const float by = sbias[col + 1];
            const int row = m0 + wm + im * 16 + g;
            float2 v0, v1;
            v0.x = acc[im][j][0] + bx; v0.y = acc[im][j][1] + by;
            v1.x = acc[im][j][2] + bx; v1.y = acc[im][j][3] + by;
            *(float2*)(g_X + (size_t)row * GG + n0 + col)       = v0;
            *(float2*)(g_X + (size_t)(row + 8) * GG + n0 + col) = v1;
        }
    }
}

// ============================================================================
// 3) LSTM recurrence (unchanged — passing R4 version)
// ============================================================================
__global__ __launch_bounds__(512, 1) void lstm_kernel(const float* __restrict__ R)
{
    extern __shared__ unsigned char sm_raw[];
    unsigned* R2   = (unsigned*)sm_raw;
    float*    hbuf = (float*)(sm_raw + 131072);
    float*    zbuf = (float*)(sm_raw + 131072 + 2048);

    const int j   = threadIdx.x;
    const int r0  = blockIdx.x * 2;

    #pragma unroll 4
    for (int p = 0; p < 64; p++) {
        float rv0 = R[(size_t)(2 * p) * GG + j];
        float rv1 = R[(size_t)(2 * p + 1) * GG + j];
        unsigned lo = (unsigned)__bfloat16_as_ushort(__float2bfloat16(rv0));
        unsigned hi = (unsigned)__bfloat16_as_ushort(__float2bfloat16(rv1));
        R2[p * 512 + j] = (hi << 16) | lo;
    }
    hbuf[j] = 0.f;
    __syncthreads();

    const float* __restrict__ px0 = g_X + (size_t)r0 * TT * GG + j;
    const float* __restrict__ px1 = g_X + (size_t)(r0 + 1) * TT * GG + j;
    float xc0 = px0[0];
    float xc1 = px1[0];

    const int grow = j >> 7;
    const int gk   = j & 127;
    float c = 0.f;

    int cur = 0;
    for (int t = 0; t < TT; t++) {
        float a0a = xc0, a0b = 0.f, a1a = xc1, a1b = 0.f;
        if (t + 1 < TT) {
            xc0 = px0[(size_t)(t + 1) * GG];
            xc1 = px1[(size_t)(t + 1) * GG];
        }
        const unsigned* __restrict__ Rcol = R2 + j;
        const float4*   __restrict__ hb   = (const float4*)(hbuf + cur * 256);
        #pragma unroll 16
        for (int p = 0; p < 64; p++) {
            unsigned w = Rcol[p * 512];
            float4 hv = hb[p];
            float f0 = __uint_as_float(w << 16);
            float f1 = __uint_as_float(w & 0xffff0000u);
            a0a = fmaf(hv.x, f0, a0a);
            a0b = fmaf(hv.y, f1, a0b);
            a1a = fmaf(hv.z, f0, a1a);
            a1b = fmaf(hv.w, f1, a1b);
        }
        zbuf[j]       = a0a + a0b;
        zbuf[512 + j] = a1a + a1b;
        __syncthreads();

        if (j < 256) {
            const float* zr = zbuf + grow * 512;
            float iz = zr[gk];
            float fz = zr[gk + 128];
            float gz = zr[gk + 256];
            float oz = zr[gk + 384];
            c = sigmoidf_(fz) * c + sigmoidf_(iz) * tanhf(gz);
            float h = sigmoidf_(oz) * tanhf(c);
            hbuf[(cur ^ 1) * 256 + (gk >> 1) * 4 + (gk & 1) + 2 * grow] = h;
            g_hs[((size_t)(r0 + grow) * TT + t) * HH + gk] = h;
        }
        __syncthreads();
        cur ^= 1;
    }
}

// ============================================================================
// 4) Heads + generator + loss (unchanged — passing R4 version)
// ============================================================================
__global__ __launch_bounds__(256) void loss_kernel(
    const float* __restrict__ obs,
    const float* __restrict__ Wrm, const float* __restrict__ brm,
    const float* __restrict__ Wrs, const float* __restrict__ brs,
    const float* __restrict__ Wgm, const float* __restrict__ bgm,
    const float* __restrict__ Wgs, const float* __restrict__ bgs)
{
    extern __shared__ float sm[];
    float* sWrm = sm;
    float* sWrs = sWrm + 8192;
    float* sWgm = sWrs + 8192;
    float* sWgs = sWgm + 8192;
    float* shs  = sWgs + 8192;
    float* spm  = shs + 8192;
    float* sred = spm + 4096;

    const int tid = threadIdx.x;
    const int m0  = blockIdx.x * 64;

    for (int idx = tid; idx < 8192; idx += 256) {
        sWrm[idx] = Wrm[idx];
        sWrs[idx] = Wrs[idx];
        sWgm[idx] = Wgm[idx];
        sWgs[idx] = Wgs[idx];
        shs[idx]  = g_hs[(size_t)m0 * HH + idx];
    }
    __syncthreads();

    float klp = 0.f, rec = 0.f;

    {
        const int s = tid & 63;
        const int rbase = tid >> 6;
        const float bm = brm[s];
        const float bsv = brs[s];
        #pragma unroll 1
        for (int it = 0; it < 16; it++) {
            const int r = rbase + (it << 2);
            const float* hrow = shs + r * HH;
            float am = bm, as = bsv;
            #pragma unroll 8
            for (int i = 0; i < HH; i++) {
                float h = hrow[i];
                am = fmaf(h, sWrm[i * 64 + s], am);
                as = fmaf(h, sWrs[i * 64 + s], as);
            }
            float sp = softplusf(as);
            size_t idx = (size_t)(m0 + r) * SS + s;
            float dm = am - g_pm[idx];
            klp += g_logsq[idx] - logf(sp)
                 + (sp * sp + dm * dm) * g_i2s2[idx] - 0.5f;
            spm[r * 64 + s] = am;
        }
    }
    __syncthreads();

    {
        const int o = tid & 127;
        const int rbase = tid >> 7;
        const float bm = bgm[o];
        const float bsv = bgs[o];
        #pragma unroll 1
        for (int it = 0; it < 32; it++) {
            const int r = rbase + (it << 1);
            const float* prow = spm + r * 64;
            float am = bm, as = bsv;
            #pragma unroll 8
            for (int s = 0; s < 64; s++) {
                float p = prow[s];
                am = fmaf(p, sWgm[s * 128 + o], am);
                as = fmaf(p, sWgs[s * 128 + o], as);
            }
            float os = softplusf(as);
            float ob = obs[(size_t)(m0 + r) * OO + o];
            float d = (ob - am) / os;
            rec += 0.5f * d * d + logf(os) + 0.91893853320467274f;
        }
    }

    sred[tid]       = klp;
    sred[256 + tid] = rec;
    __syncthreads();
    #pragma unroll
    for (int st = 128; st > 0; st >>= 1) {
        if (tid < st) {
            sred[tid]       += sred[tid + st];
            sred[256 + tid] += sred[256 + tid + st];
        }
        __syncthreads();
    }
    if (tid == 0) {
        g_part[blockIdx.x * 2]     = sred[0];
        g_part[blockIdx.x * 2 + 1] = sred[256];
    }
}

// ============================================================================
// 5) Final deterministic reduce
// ============================================================================
__global__ __launch_bounds__(256) void reduce_kernel(float* __restrict__ out)
{
    __shared__ double sk[256];
    __shared__ double sr[256];
    const int tid = threadIdx.x;
    double k = 0.0, r = 0.0;
    for (int i = tid; i < LOSS_BLOCKS; i += 256) {
        k += (double)g_part[2 * i];
        r += (double)g_part[2 * i + 1];
    }
    sk[tid] = k; sr[tid] = r;
    __syncthreads();
    #pragma unroll
    for (int st = 128; st > 0; st >>= 1) {
        if (tid < st) { sk[tid] += sk[tid + st]; sr[tid] += sr[tid + st]; }
        __syncthreads();
    }
    if (tid == 0)
        out[0] = (float)(sk[0] / ((double)BB * (double)TT) + sr[0] / (double)BB);
}

// ============================================================================
// launch
// ============================================================================
extern "C" void kernel_launch(void* const* d_in, const int* in_sizes, int n_in,
                              void* d_out, int out_size)
{
    const float* obs = (const float*)d_in[0];
    const float* im  = (const float*)d_in[1];
    const float* Wfm = (const float*)d_in[3];
    const float* bfm = (const float*)d_in[4];
    const float* Wfs = (const float*)d_in[5];
    const float* bfs = (const float*)d_in[6];
    const float* Wgm = (const float*)d_in[7];
    const float* bgm = (const float*)d_in[8];
    const float* Wgs = (const float*)d_in[9];
    const float* bgs = (const float*)d_in[10];
    const float* K   = (const float*)d_in[11];
    const float* R   = (const float*)d_in[12];
    const float* bl  = (const float*)d_in[13];
    const float* Wrm = (const float*)d_in[14];
    const float* brm = (const float*)d_in[15];
    const float* Wrs = (const float*)d_in[16];
    const float* brs = (const float*)d_in[17];

    const int LSTM_SMEM = 131072 + 2048 + 4096;
    const int LOSS_SMEM = (8192 * 5 + 4096 + 512) * 4;
    cudaFuncSetAttribute(lstm_kernel, cudaFuncAttributeMaxDynamicSharedMemorySize, LSTM_SMEM);
    cudaFuncSetAttribute(loss_kernel, cudaFuncAttributeMaxDynamicSharedMemorySize, LOSS_SMEM);
    cudaFuncSetAttribute(xgemm_mma,   cudaFuncAttributeMaxDynamicSharedMemorySize, XSM_TOT);

    conv_kernel<<<(MT * OO / 4) / 256, 256>>>(obs);
    kt_kernel<<<GG, 128>>>(K);
    prior_kernel<<<BB, 64>>>(im, Wfm, bfm, Wfs, bfs);
    xgemm_mma<<<dim3(MT / 128, GG / 128), 256, XSM_TOT>>>(bl);
    lstm_kernel<<<BB / 2, 512, LSTM_SMEM>>>(R);
    loss_kernel<<<LOSS_BLOCKS, 256, LOSS_SMEM>>>(obs, Wrm, brm, Wrs, brs,
                                                 Wgm, bgm, Wgs, bgs);
    reduce_kernel<<<1, 256>>>((float*)d_out);
}

// round 15
// speedup vs baseline: 1.8956x; 1.6742x over previous
#include <cuda_runtime.h>
#include <cuda_bf16.h>
#include <math.h>
#include <stdint.h>

// Problem constants
#define BB 256      // batch
#define TT 512      // seq len
#define SS 64       // state dim
#define OO 128      // obs dim
#define HH 128      // LSTM hidden
#define GG 512      // 4*H
#define MT (BB*TT)  // 131072 flattened rows

// ---------------- scratch (static __device__ — no allocation) ----------------
__device__ float g_pm   [(size_t)MT * SS];        // prior mean
__device__ float g_logsq[(size_t)MT * SS];        // log(prior_scale)
__device__ float g_i2s2 [(size_t)MT * SS];        // 0.5 / prior_scale^2
__device__ float g_X    [(size_t)MT * GG];        // obs @ K_lstm + b_lstm
__device__ __nv_bfloat16 g_hsb[(size_t)MT * HH];  // LSTM hidden states (bf16)
__device__ __nv_bfloat16 g_Abf[(size_t)MT * OO];  // obs in bf16
__device__ __nv_bfloat16 g_Kt [(size_t)GG * OO];  // K_lstm^T [N,K] bf16
__device__ __nv_bfloat16 g_Wrt[128 * 128];        // [Wrm|Wrs]^T [n=128,k=128] bf16
__device__ __nv_bfloat16 g_Wgt[256 * 64];         // [Wgm|Wgs]^T [n=256,k=64] bf16
__device__ float g_P [(size_t)MT * 128];          // post_mean(0:64) | post_scale_pre(64:128)
__device__ __nv_bfloat16 g_pmb[(size_t)MT * 64];  // post_mean bf16 (G2 input)
__device__ float g_Q [(size_t)MT * 256];          // obs_mean(0:128) | obs_scale_pre(128:256)
#define LOSS_BLOCKS 2048
__device__ float g_part [LOSS_BLOCKS * 2];

// ---------------- helpers ----------------
__device__ __forceinline__ uint32_t smem_u32(const void* p) {
    uint32_t a;
    asm("{ .reg .u64 t; cvta.to.shared.u64 t, %1; cvt.u32.u64 %0, t; }" : "=r"(a) : "l"(p));
    return a;
}
__device__ __forceinline__ float softplusf(float x) {
    return (x > 0.f) ? (x + log1pf(expf(-x))) : log1pf(expf(x));
}
__device__ __forceinline__ float softplus_fast(float x) {
    // margin analysis: x here is O(1); guard large x for safety
    return (x > 15.f) ? x : __logf(1.f + __expf(x));
}
__device__ __forceinline__ float tanh_fast(float x) {
    float y;
    asm("tanh.approx.f32 %0, %1;" : "=f"(y) : "f"(x));
    return y;
}
__device__ __forceinline__ float sigmoid_fast(float x) {
    return fmaf(tanh_fast(0.5f * x), 0.5f, 0.5f);
}

// ============================================================================
// 0a) Convert obs -> bf16
// ============================================================================
__global__ __launch_bounds__(256) void conv_kernel(const float* __restrict__ obs)
{
    size_t i = (size_t)blockIdx.x * 256 + threadIdx.x;   // over MT*OO/4
    float4 v = ((const float4*)obs)[i];
    __nv_bfloat162* dst = (__nv_bfloat162*)g_Abf;
    dst[2 * i]     = __floats2bfloat162_rn(v.x, v.y);
    dst[2 * i + 1] = __floats2bfloat162_rn(v.z, v.w);
}

// 0b) Transpose K_lstm [128,512] -> g_Kt [512,128] bf16
__global__ __launch_bounds__(128) void kt_kernel(const float* __restrict__ K)
{
    int n = blockIdx.x;           // 0..511
    int k = threadIdx.x;          // 0..127
    g_Kt[(size_t)n * OO + k] = __float2bfloat16(K[(size_t)k * GG + n]);
}

// 0c) Pack [Wrm | Wrs] -> g_Wrt [n=128][k=128] bf16 (Wr* are [H=128, S=64])
__global__ __launch_bounds__(128) void wr_pack(const float* __restrict__ Wrm,
                                               const float* __restrict__ Wrs)
{
    int n = blockIdx.x;           // 0..127
    int k = threadIdx.x;          // 0..127
    float v = (n < 64) ? Wrm[k * 64 + n] : Wrs[k * 64 + (n - 64)];
    g_Wrt[n * 128 + k] = __float2bfloat16(v);
}

// 0d) Pack [Wgm | Wgs] -> g_Wgt [n=256][k=64] bf16 (Wg* are [S=64, O=128])
__global__ __launch_bounds__(64) void wg_pack(const float* __restrict__ Wgm,
                                              const float* __restrict__ Wgs)
{
    int n = blockIdx.x;           // 0..255
    int k = threadIdx.x;          // 0..63
    float v = (n < 128) ? Wgm[k * 128 + n] : Wgs[k * 128 + (n - 128)];
    g_Wgt[n * 64 + k] = __float2bfloat16(v);
}

// ============================================================================
// 1) Prior rollout (unchanged — passing version)
// ============================================================================
__global__ __launch_bounds__(64) void prior_kernel(
    const float* __restrict__ im, const float* __restrict__ Wfm,
    const float* __restrict__ bfm, const float* __restrict__ Wfs,
    const float* __restrict__ bfs)
{
    __shared__ float sWm[SS * SS];
    __shared__ float sWs[SS * SS];
    __shared__ float m[2][SS];

    const int j = threadIdx.x;
    const int b = blockIdx.x;

    for (int idx = j; idx < SS * SS; idx += 64) {
        sWm[idx] = Wfm[idx];
        sWs[idx] = Wfs[idx];
    }
    const float bm = bfm[j];
    const float bs = bfs[j];
    m[0][j] = im[b * SS + j];
    __syncthreads();

    float* __restrict__ pmb = g_pm    + (size_t)b * TT * SS;
    float* __restrict__ lqb = g_logsq + (size_t)b * TT * SS;
    float* __restrict__ isb = g_i2s2  + (size_t)b * TT * SS;

    int cur = 0;
    for (int t = 0; t < TT; t++) {
        float am0 = bm, am1 = 0.f, as0 = bs, as1 = 0.f;
        #pragma unroll 8
        for (int i = 0; i < SS; i += 2) {
            float mi0 = m[cur][i];
            float mi1 = m[cur][i + 1];
            am0 = fmaf(mi0, sWm[i * SS + j], am0);
            am1 = fmaf(mi1, sWm[(i + 1) * SS + j], am1);
            as0 = fmaf(mi0, sWs[i * SS + j], as0);
            as1 = fmaf(mi1, sWs[(i + 1) * SS + j], as1);
        }
        float am = am0 + am1;
        float sp = softplusf(as0 + as1);

        pmb[t * SS + j] = am;
        lqb[t * SS + j] = logf(sp);
        isb[t * SS + j] = 0.5f / (sp * sp);

        m[cur ^ 1][j] = am;
        __syncthreads();
        cur ^= 1;
    }
}

// ============================================================================
// 2) X = obs @ K_lstm + b_lstm via HMMA (unchanged — passing R8 version)
// ============================================================================
#define XSTR 136
#define XSM_A 0
#define XSM_B (128 * XSTR * 2)
#define XSM_BIAS (2 * 128 * XSTR * 2)
#define XSM_TOT (XSM_BIAS + 128 * 4)

__global__ __launch_bounds__(256, 2) void xgemm_mma(const float* __restrict__ bias)
{
    extern __shared__ unsigned char smraw[];
    __nv_bfloat16* sA = (__nv_bfloat16*)(smraw + XSM_A);
    __nv_bfloat16* sB = (__nv_bfloat16*)(smraw + XSM_B);
    float* sbias = (float*)(smraw + XSM_BIAS);

    const int tid  = threadIdx.x;
    const int lane = tid & 31;
    const int wid  = tid >> 5;
    const int m0 = blockIdx.x * 128;
    const int n0 = blockIdx.y * 128;

    {
        const int r  = tid >> 4;
        const int cc = (tid & 15) * 8;
        #pragma unroll
        for (int i = 0; i < 8; i++) {
            int row = r + i * 16;
            uint4 va = *(const uint4*)(g_Abf + (size_t)(m0 + row) * OO + cc);
            *(uint4*)(sA + row * XSTR + cc) = va;
            uint4 vb = *(const uint4*)(g_Kt + (size_t)(n0 + row) * OO + cc);
            *(uint4*)(sB + row * XSTR + cc) = vb;
        }
    }
    if (tid < 128) sbias[tid] = bias[n0 + tid];
    __syncthreads();

    const int wm = (wid & 3) * 32;
    const int wn = (wid >> 2) * 64;
    const uint32_t sA_u = smem_u32(sA);
    const uint32_t sB_u = smem_u32(sB);

    float acc[2][8][4];
    #pragma unroll
    for (int im = 0; im < 2; im++)
        #pragma unroll
        for (int j = 0; j < 8; j++)
            #pragma unroll
            for (int c = 0; c < 4; c++) acc[im][j][c] = 0.f;

    const int q  = lane >> 3;
    const int r8 = lane & 7;

    #pragma unroll
    for (int kk = 0; kk < 8; kk++) {
        const int k0 = kk * 16;
        uint32_t ra[2][4];
        #pragma unroll
        for (int im = 0; im < 2; im++) {
            int row = wm + im * 16 + (q & 1) * 8 + r8;
            int col = k0 + (q >> 1) * 8;
            uint32_t addr = sA_u + (uint32_t)((row * XSTR + col) * 2);
            asm volatile(
                "ldmatrix.sync.aligned.m8n8.x4.shared.b16 {%0,%1,%2,%3}, [%4];"
                : "=r"(ra[im][0]), "=r"(ra[im][1]), "=r"(ra[im][2]), "=r"(ra[im][3])
                : "r"(addr));
        }
        uint32_t rb[8][2];
        #pragma unroll
        for (int jn = 0; jn < 4; jn++) {
            int row = wn + jn * 16 + (q >> 1) * 8 + r8;
            int col = k0 + (q & 1) * 8;
            uint32_t addr = sB_u + (uint32_t)((row * XSTR + col) * 2);
            asm volatile(
                "ldmatrix.sync.aligned.m8n8.x4.shared.b16 {%0,%1,%2,%3}, [%4];"
                : "=r"(rb[2 * jn][0]), "=r"(rb[2 * jn][1]),
                  "=r"(rb[2 * jn + 1][0]), "=r"(rb[2 * jn + 1][1])
                : "r"(addr));
        }
        #pragma unroll
        for (int im = 0; im < 2; im++)
            #pragma unroll
            for (int j = 0; j < 8; j++) {
                asm volatile(
                    "mma.sync.aligned.m16n8k16.row.col.f32.bf16.bf16.f32 "
                    "{%0,%1,%2,%3}, {%4,%5,%6,%7}, {%8,%9}, {%0,%1,%2,%3};"
                    : "+f"(acc[im][j][0]), "+f"(acc[im][j][1]),
                      "+f"(acc[im][j][2]), "+f"(acc[im][j][3])
                    : "r"(ra[im][0]), "r"(ra[im][1]), "r"(ra[im][2]), "r"(ra[im][3]),
                      "r"(rb[j][0]), "r"(rb[j][1]));
            }
    }

    const int g  = lane >> 2;
    const int t2 = (lane & 3) * 2;
    #pragma unroll
    for (int im = 0; im < 2; im++) {
        #pragma unroll
        for (int j = 0; j < 8; j++) {
            const int col = wn + j * 8 + t2;
            const float bx = sbias[col];
            const float by = sbias[col + 1];
            const int row = m0 + wm + im * 16 + g;
            float2 v0, v1;
            v0.x = acc[im][j][0] + bx; v0.y = acc[im][j][1] + by;
            v1.x = acc[im][j][2] + bx; v1.y = acc[im][j][3] + by;
            *(float2*)(g_X + (size_t)row * GG + n0 + col)       = v0;
            *(float2*)(g_X + (size_t)(row + 8) * GG + n0 + col) = v1;
        }
    }
}

// ============================================================================
// 3) LSTM recurrence — fast activations + bf16 h store
// ============================================================================
__global__ __launch_bounds__(512, 1) void lstm_kernel(const float* __restrict__ R)
{
    extern __shared__ unsigned char sm_raw[];
    unsigned* R2   = (unsigned*)sm_raw;
    float*    hbuf = (float*)(sm_raw + 131072);
    float*    zbuf = (float*)(sm_raw + 131072 + 2048);

    const int j   = threadIdx.x;
    const int r0  = blockIdx.x * 2;

    #pragma unroll 4
    for (int p = 0; p < 64; p++) {
        float rv0 = R[(size_t)(2 * p) * GG + j];
        float rv1 = R[(size_t)(2 * p + 1) * GG + j];
        unsigned lo = (unsigned)__bfloat16_as_ushort(__float2bfloat16(rv0));
        unsigned hi = (unsigned)__bfloat16_as_ushort(__float2bfloat16(rv1));
        R2[p * 512 + j] = (hi << 16) | lo;
    }
    hbuf[j] = 0.f;
    __syncthreads();

    const float* __restrict__ px0 = g_X + (size_t)r0 * TT * GG + j;
    const float* __restrict__ px1 = g_X + (size_t)(r0 + 1) * TT * GG + j;
    float xc0 = px0[0];
    float xc1 = px1[0];

    const int grow = j >> 7;
    const int gk   = j & 127;
    float c = 0.f;

    int cur = 0;
    for (int t = 0; t < TT; t++) {
        float a0a = xc0, a0b = 0.f, a1a = xc1, a1b = 0.f;
        if (t + 1 < TT) {
            xc0 = px0[(size_t)(t + 1) * GG];
            xc1 = px1[(size_t)(t + 1) * GG];
        }
        const unsigned* __restrict__ Rcol = R2 + j;
        const float4*   __restrict__ hb   = (const float4*)(hbuf + cur * 256);
        #pragma unroll 16
        for (int p = 0; p < 64; p++) {
            unsigned w = Rcol[p * 512];
            float4 hv = hb[p];
            float f0 = __uint_as_float(w << 16);
            float f1 = __uint_as_float(w & 0xffff0000u);
            a0a = fmaf(hv.x, f0, a0a);
            a0b = fmaf(hv.y, f1, a0b);
            a1a = fmaf(hv.z, f0, a1a);
            a1b = fmaf(hv.w, f1, a1b);
        }
        zbuf[j]       = a0a + a0b;
        zbuf[512 + j] = a1a + a1b;
        __syncthreads();

        if (j < 256) {
            const float* zr = zbuf + grow * 512;
            float iz = zr[gk];
            float fz = zr[gk + 128];
            float gz = zr[gk + 256];
            float oz = zr[gk + 384];
            c = sigmoid_fast(fz) * c + sigmoid_fast(iz) * tanh_fast(gz);
            float h = sigmoid_fast(oz) * tanh_fast(c);
            hbuf[(cur ^ 1) * 256 + (gk >> 1) * 4 + (gk & 1) + 2 * grow] = h;
            g_hsb[((size_t)(r0 + grow) * TT + t) * HH + gk] = __float2bfloat16(h);
        }
        __syncthreads();
        cur ^= 1;
    }
}

// ============================================================================
// 4a) G1: P = hs @ [Wrm|Wrs] + [brm|brs]  (M=MT, N=128, K=128, HMMA)
//     Epilogue: store fp32 to g_P; cols 0-63 also store bf16 to g_pmb.
// ============================================================================
__global__ __launch_bounds__(256, 2) void g1_mma(const float* __restrict__ brm,
                                                 const float* __restrict__ brs)
{
    extern __shared__ unsigned char smraw[];
    __nv_bfloat16* sA = (__nv_bfloat16*)(smraw + XSM_A);
    __nv_bfloat16* sB = (__nv_bfloat16*)(smraw + XSM_B);
    float* sbias = (float*)(smraw + XSM_BIAS);

    const int tid  = threadIdx.x;
    const int lane = tid & 31;
    const int wid  = tid >> 5;
    const int m0 = blockIdx.x * 128;

    {
        const int r  = tid >> 4;
        const int cc = (tid & 15) * 8;
        #pragma unroll
        for (int i = 0; i < 8; i++) {
            int row = r + i * 16;
            uint4 va = *(const uint4*)(g_hsb + (size_t)(m0 + row) * HH + cc);
            *(uint4*)(sA + row * XSTR + cc) = va;
            uint4 vb = *(const uint4*)(g_Wrt + (size_t)row * 128 + cc);
            *(uint4*)(sB + row * XSTR + cc) = vb;
        }
    }
    if (tid < 128) sbias[tid] = (tid < 64) ? brm[tid] : brs[tid - 64];
    __syncthreads();

    const int wm = (wid & 3) * 32;
    const int wn = (wid >> 2) * 64;
    const uint32_t sA_u = smem_u32(sA);
    const uint32_t sB_u = smem_u32(sB);

    float acc[2][8][4];
    #pragma unroll
    for (int im = 0; im < 2; im++)
        #pragma unroll
        for (int j = 0; j < 8; j++)
            #pragma unroll
            for (int c = 0; c < 4; c++) acc[im][j][c] = 0.f;

    const int q  = lane >> 3;
    const int r8 = lane & 7;

    #pragma unroll
    for (int kk = 0; kk < 8; kk++) {
        const int k0 = kk * 16;
        uint32_t ra[2][4];
        #pragma unroll
        for (int im = 0; im < 2; im++) {
            int row = wm + im * 16 + (q & 1) * 8 + r8;
            int col = k0 + (q >> 1) * 8;
            uint32_t addr = sA_u + (uint32_t)((row * XSTR + col) * 2);
            asm volatile(
                "ldmatrix.sync.aligned.m8n8.x4.shared.b16 {%0,%1,%2,%3}, [%4];"
                : "=r"(ra[im][0]), "=r"(ra[im][1]), "=r"(ra[im][2]), "=r"(ra[im][3])
                : "r"(addr));
        }
        uint32_t rb[8][2];
        #pragma unroll
        for (int jn = 0; jn < 4; jn++) {
            int row = wn + jn * 16 + (q >> 1) * 8 + r8;
            int col = k0 + (q & 1) * 8;
            uint32_t addr = sB_u + (uint32_t)((row * XSTR + col) * 2);
            asm volatile(
                "ldmatrix.sync.aligned.m8n8.x4.shared.b16 {%0,%1,%2,%3}, [%4];"
                : "=r"(rb[2 * jn][0]), "=r"(rb[2 * jn][1]),
                  "=r"(rb[2 * jn + 1][0]), "=r"(rb[2 * jn + 1][1])
                : "r"(addr));
        }
        #pragma unroll
        for (int im = 0; im < 2; im++)
            #pragma unroll
            for (int j = 0; j < 8; j++) {
                asm volatile(
                    "mma.sync.aligned.m16n8k16.row.col.f32.bf16.bf16.f32 "
                    "{%0,%1,%2,%3}, {%4,%5,%6,%7}, {%8,%9}, {%0,%1,%2,%3};"
                    : "+f"(acc[im][j][0]), "+f"(acc[im][j][1]),
                      "+f"(acc[im][j][2]), "+f"(acc[im][j][3])
                    : "r"(ra[im][0]), "r"(ra[im][1]), "r"(ra[im][2]), "r"(ra[im][3]),
                      "r"(rb[j][0]), "r"(rb[j][1]));
            }
    }

    const int g  = lane >> 2;
    const int t2 = (lane & 3) * 2;
    #pragma unroll
    for (int im = 0; im < 2; im++) {
        #pragma unroll
        for (int j = 0; j < 8; j++) {
            const int col = wn + j * 8 + t2;
            const float bx = sbias[col];
            const float by = sbias[col + 1];
            const int row = m0 + wm + im * 16 + g;
            float2 v0, v1;
            v0.x = acc[im][j][0] + bx; v0.y = acc[im][j][1] + by;
            v1.x = acc[im][j][2] + bx; v1.y = acc[im][j][3] + by;
            *(float2*)(g_P + (size_t)row * 128 + col)       = v0;
            *(float2*)(g_P + (size_t)(row + 8) * 128 + col) = v1;
            if (wn == 0) {  // post_mean -> bf16 for generator GEMM
                *(__nv_bfloat162*)(g_pmb + (size_t)row * 64 + col)
                    = __floats2bfloat162_rn(v0.x, v0.y);
                *(__nv_bfloat162*)(g_pmb + (size_t)(row + 8) * 64 + col)
                    = __floats2bfloat162_rn(v1.x, v1.y);
            }
        }
    }
}

// ============================================================================
// 4b) G2: Q = post_mean @ [Wgm|Wgs] + [bgm|bgs]  (M=MT, N=256 (2x128), K=64)
// ============================================================================
#define YSTR 72
#define YSM_A 0
#define YSM_B (128 * YSTR * 2)
#define YSM_BIAS (2 * 128 * YSTR * 2)
#define YSM_TOT (YSM_BIAS + 128 * 4)

__global__ __launch_bounds__(256, 2) void g2_mma(const float* __restrict__ bgm,
                                                 const float* __restrict__ bgs)
{
    extern __shared__ unsigned char smraw[];
    __nv_bfloat16* sA = (__nv_bfloat16*)(smraw + YSM_A);
    __nv_bfloat16* sB = (__nv_bfloat16*)(smraw + YSM_B);
    float* sbias = (float*)(smraw + YSM_BIAS);

    const int tid  = threadIdx.x;
    const int lane = tid & 31;
    const int wid  = tid >> 5;
    const int m0 = blockIdx.x * 128;
    const int ny = blockIdx.y;           // 0: mean, 1: scale

    {
        const int r  = tid >> 3;          // 0..31
        const int cc = (tid & 7) * 8;     // 0..56
        #pragma unroll
        for (int i = 0; i < 4; i++) {
            int row = r + i * 32;
            uint4 va = *(const uint4*)(g_pmb + (size_t)(m0 + row) * 64 + cc);
            *(uint4*)(sA + row * YSTR + cc) = va;
            uint4 vb = *(const uint4*)(g_Wgt + (size_t)(ny * 128 + row) * 64 + cc);
            *(uint4*)(sB + row * YSTR + cc) = vb;
        }
    }
    if (tid < 128) sbias[tid] = ny ? bgs[tid] : bgm[tid];
    __syncthreads();

    const int wm = (wid & 3) * 32;
    const int wn = (wid >> 2) * 64;
    const uint32_t sA_u = smem_u32(sA);
    const uint32_t sB_u = smem_u32(sB);

    float acc[2][8][4];
    #pragma unroll
    for (int im = 0; im < 2; im++)
        #pragma unroll
        for (int j = 0; j < 8; j++)
            #pragma unroll
            for (int c = 0; c < 4; c++) acc[im][j][c] = 0.f;

    const int q  = lane >> 3;
    const int r8 = lane & 7;

    #pragma unroll
    for (int kk = 0; kk < 4; kk++) {
        const int k0 = kk * 16;
        uint32_t ra[2][4];
        #pragma unroll
        for (int im = 0; im < 2; im++) {
            int row = wm + im * 16 + (q & 1) * 8 + r8;
            int col = k0 + (q >> 1) * 8;
            uint32_t addr = sA_u + (uint32_t)((row * YSTR + col) * 2);
            asm volatile(
                "ldmatrix.sync.aligned.m8n8.x4.shared.b16 {%0,%1,%2,%3}, [%4];"
                : "=r"(ra[im][0]), "=r"(ra[im][1]), "=r"(ra[im][2]), "=r"(ra[im][3])
                : "r"(addr));
        }
        uint32_t rb[8][2];
        #pragma unroll
        for (int jn = 0; jn < 4; jn++) {
            int row = wn + jn * 16 + (q >> 1) * 8 + r8;
            int col = k0 + (q & 1) * 8;
            uint32_t addr = sB_u + (uint32_t)((row * YSTR + col) * 2);
            asm volatile(
                "ldmatrix.sync.aligned.m8n8.x4.shared.b16 {%0,%1,%2,%3}, [%4];"
                : "=r"(rb[2 * jn][0]), "=r"(rb[2 * jn][1]),
                  "=r"(rb[2 * jn + 1][0]), "=r"(rb[2 * jn + 1][1])
                : "r"(addr));
        }
        #pragma unroll
        for (int im = 0; im < 2; im++)
            #pragma unroll
            for (int j = 0; j < 8; j++) {
                asm volatile(
                    "mma.sync.aligned.m16n8k16.row.col.f32.bf16.bf16.f32 "
                    "{%0,%1,%2,%3}, {%4,%5,%6,%7}, {%8,%9}, {%0,%1,%2,%3};"
                    : "+f"(acc[im][j][0]), "+f"(acc[im][j][1]),
                      "+f"(acc[im][j][2]), "+f"(acc[im][j][3])
                    : "r"(ra[im][0]), "r"(ra[im][1]), "r"(ra[im][2]), "r"(ra[im][3]),
                      "r"(rb[j][0]), "r"(rb[j][1]));
            }
    }

    const int g  = lane >> 2;
    const int t2 = (lane & 3) * 2;
    #pragma unroll
    for (int im = 0; im < 2; im++) {
        #pragma unroll
        for (int j = 0; j < 8; j++) {
            const int col = wn + j * 8 + t2;
            const float bx = sbias[col];
            const float by = sbias[col + 1];
            const int row = m0 + wm + im * 16 + g;
            float2 v0, v1;
            v0.x = acc[im][j][0] + bx; v0.y = acc[im][j][1] + by;
            v1.x = acc[im][j][2] + bx; v1.y = acc[im][j][3] + by;
            *(float2*)(g_Q + (size_t)row * 256 + ny * 128 + col)       = v0;
            *(float2*)(g_Q + (size_t)(row + 8) * 256 + ny * 128 + col) = v1;
        }
    }
}

// ============================================================================
// 4c) Elementwise KL + reconstruction, block partials
// ============================================================================
__global__ __launch_bounds__(256) void lossew_kernel(const float* __restrict__ obs)
{
    __shared__ float sred[512];
    const int tid = threadIdx.x;

    float klp = 0.f, rec = 0.f;

    // KL over MT*64 elements: 2048 blocks x 4096
    {
        size_t base = (size_t)blockIdx.x * 4096 + tid;
        #pragma unroll 4
        for (int k = 0; k < 16; k++) {
            size_t idx = base + (size_t)k * 256;
            size_t row = idx >> 6;
            int s = (int)(idx & 63);
            float pm  = g_P[row * 128 + s];
            float pre = g_P[row * 128 + 64 + s];
            float sp  = softplus_fast(pre);
            float dm  = pm - g_pm[idx];
            klp += g_logsq[idx] - __logf(sp)
                 + (sp * sp + dm * dm) * g_i2s2[idx] - 0.5f;
        }
    }
    // recon over MT*128 elements: 2048 blocks x 8192
    {
        size_t base = (size_t)blockIdx.x * 8192 + tid;
        #pragma unroll 4
        for (int k = 0; k < 32; k++) {
            size_t idx = base + (size_t)k * 256;
            size_t row = idx >> 7;
            int o = (int)(idx & 127);
            float om  = g_Q[row * 256 + o];
            float osp = g_Q[row * 256 + 128 + o];
            float os  = softplus_fast(osp);
            float d   = (obs[idx] - om) * __frcp_rn(os);
            rec += 0.5f * d * d + __logf(os) + 0.91893853320467274f;
        }
    }

    sred[tid]       = klp;
    sred[256 + tid] = rec;
    __syncthreads();
    #pragma unroll
    for (int st = 128; st > 0; st >>= 1) {
        if (tid < st) {
            sred[tid]       += sred[tid + st];
            sred[256 + tid] += sred[256 + tid + st];
        }
        __syncthreads();
    }
    if (tid == 0) {
        g_part[blockIdx.x * 2]     = sred[0];
        g_part[blockIdx.x * 2 + 1] = sred[256];
    }
}

// ============================================================================
// 5) Final deterministic reduce
// ============================================================================
__global__ __launch_bounds__(256) void reduce_kernel(float* __restrict__ out)
{
    __shared__ double sk[256];
    __shared__ double sr[256];
    const int tid = threadIdx.x;
    double k = 0.0, r = 0.0;
    for (int i = tid; i < LOSS_BLOCKS; i += 256) {
        k += (double)g_part[2 * i];
        r += (double)g_part[2 * i + 1];
    }
    sk[tid] = k; sr[tid] = r;
    __syncthreads();
    #pragma unroll
    for (int st = 128; st > 0; st >>= 1) {
        if (tid < st) { sk[tid] += sk[tid + st]; sr[tid] += sr[tid + st]; }
        __syncthreads();
    }
    if (tid == 0)
        out[0] = (float)(sk[0] / ((double)BB * (double)TT) + sr[0] / (double)BB);
}

// ============================================================================
// launch
// ============================================================================
extern "C" void kernel_launch(void* const* d_in, const int* in_sizes, int n_in,
                              void* d_out, int out_size)
{
    const float* obs = (const float*)d_in[0];
    const float* im  = (const float*)d_in[1];
    const float* Wfm = (const float*)d_in[3];
    const float* bfm = (const float*)d_in[4];
    const float* Wfs = (const float*)d_in[5];
    const float* bfs = (const float*)d_in[6];
    const float* Wgm = (const float*)d_in[7];
    const float* bgm = (const float*)d_in[8];
    const float* Wgs = (const float*)d_in[9];
    const float* bgs = (const float*)d_in[10];
    const float* K   = (const float*)d_in[11];
    const float* R   = (const float*)d_in[12];
    const float* bl  = (const float*)d_in[13];
    const float* Wrm = (const float*)d_in[14];
    const float* brm = (const float*)d_in[15];
    const float* Wrs = (const float*)d_in[16];
    const float* brs = (const float*)d_in[17];

    const int LSTM_SMEM = 131072 + 2048 + 4096;
    cudaFuncSetAttribute(lstm_kernel, cudaFuncAttributeMaxDynamicSharedMemorySize, LSTM_SMEM);
    cudaFuncSetAttribute(xgemm_mma,   cudaFuncAttributeMaxDynamicSharedMemorySize, XSM_TOT);
    cudaFuncSetAttribute(g1_mma,      cudaFuncAttributeMaxDynamicSharedMemorySize, XSM_TOT);
    cudaFuncSetAttribute(g2_mma,      cudaFuncAttributeMaxDynamicSharedMemorySize, YSM_TOT);

    conv_kernel<<<(MT * OO / 4) / 256, 256>>>(obs);
    kt_kernel<<<GG, 128>>>(K);
    wr_pack<<<128, 128>>>(Wrm, Wrs);
    wg_pack<<<256, 64>>>(Wgm, Wgs);
    prior_kernel<<<BB, 64>>>(im, Wfm, bfm, Wfs, bfs);
    xgemm_mma<<<dim3(MT / 128, GG / 128), 256, XSM_TOT>>>(bl);
    lstm_kernel<<<BB / 2, 512, LSTM_SMEM>>>(R);
    g1_mma<<<MT / 128, 256, XSM_TOT>>>(brm, brs);
    g2_mma<<<dim3(MT / 128, 2), 256, YSM_TOT>>>(bgm, bgs);
    lossew_kernel<<<LOSS_BLOCKS, 256>>>(obs);
    reduce_kernel<<<1, 256>>>((float*)d_out);
}

// round 16
// speedup vs baseline: 2.4937x; 1.3155x over previous
#include <cuda_runtime.h>
#include <cuda_bf16.h>
#include <math.h>
#include <stdint.h>

// Problem constants
#define BB 256      // batch
#define TT 512      // seq len
#define SS 64       // state dim
#define OO 128      // obs dim
#define HH 128      // LSTM hidden
#define GG 512      // 4*H
#define MT (BB*TT)  // 131072 flattened rows

// ---------------- scratch (static __device__ — no allocation) ----------------
__device__ float g_pm   [(size_t)MT * SS];        // prior mean
__device__ float g_logsq[(size_t)MT * SS];        // log(prior_scale)
__device__ float g_i2s2 [(size_t)MT * SS];        // 0.5 / prior_scale^2
__device__ float g_X    [(size_t)MT * GG];        // obs @ K_lstm + b_lstm
__device__ __nv_bfloat16 g_hsb[(size_t)MT * HH];  // LSTM hidden states (bf16)
__device__ __nv_bfloat16 g_Abf[(size_t)MT * OO];  // obs in bf16
__device__ __nv_bfloat16 g_Kt [(size_t)GG * OO];  // K_lstm^T [N,K] bf16
__device__ __nv_bfloat16 g_Rt [(size_t)GG * HH];  // R_lstm^T [N=512,K=128] bf16
__device__ __nv_bfloat16 g_Wrt[128 * 128];        // [Wrm|Wrs]^T [n=128,k=128] bf16
__device__ __nv_bfloat16 g_Wgt[256 * 64];         // [Wgm|Wgs]^T [n=256,k=64] bf16
__device__ float g_P [(size_t)MT * 128];          // post_mean(0:64) | post_scale_pre(64:128)
__device__ __nv_bfloat16 g_pmb[(size_t)MT * 64];  // post_mean bf16 (G2 input)
__device__ float g_Q [(size_t)MT * 256];          // obs_mean(0:128) | obs_scale_pre(128:256)
#define LOSS_BLOCKS 2048
__device__ float g_part [LOSS_BLOCKS * 2];

// ---------------- helpers ----------------
__device__ __forceinline__ uint32_t smem_u32(const void* p) {
    uint32_t a;
    asm("{ .reg .u64 t; cvta.to.shared.u64 t, %1; cvt.u32.u64 %0, t; }" : "=r"(a) : "l"(p));
    return a;
}
__device__ __forceinline__ float softplusf(float x) {
    return (x > 0.f) ? (x + log1pf(expf(-x))) : log1pf(expf(x));
}
__device__ __forceinline__ float softplus_fast(float x) {
    return (x > 15.f) ? x : __logf(1.f + __expf(x));
}
__device__ __forceinline__ float tanh_fast(float x) {
    float y;
    asm("tanh.approx.f32 %0, %1;" : "=f"(y) : "f"(x));
    return y;
}
__device__ __forceinline__ float sigmoid_fast(float x) {
    return fmaf(tanh_fast(0.5f * x), 0.5f, 0.5f);
}

// ============================================================================
// 0a) Convert obs -> bf16
// ============================================================================
__global__ __launch_bounds__(256) void conv_kernel(const float* __restrict__ obs)
{
    size_t i = (size_t)blockIdx.x * 256 + threadIdx.x;
    float4 v = ((const float4*)obs)[i];
    __nv_bfloat162* dst = (__nv_bfloat162*)g_Abf;
    dst[2 * i]     = __floats2bfloat162_rn(v.x, v.y);
    dst[2 * i + 1] = __floats2bfloat162_rn(v.z, v.w);
}

// 0b) Transpose K_lstm [128,512] -> g_Kt [512,128] bf16
__global__ __launch_bounds__(128) void kt_kernel(const float* __restrict__ K)
{
    int n = blockIdx.x;
    int k = threadIdx.x;
    g_Kt[(size_t)n * OO + k] = __float2bfloat16(K[(size_t)k * GG + n]);
}

// 0b') Transpose R_lstm [128,512] -> g_Rt [512,128] bf16
__global__ __launch_bounds__(128) void rt_pack(const float* __restrict__ R)
{
    int n = blockIdx.x;           // 0..511
    int k = threadIdx.x;          // 0..127
    g_Rt[(size_t)n * HH + k] = __float2bfloat16(R[(size_t)k * GG + n]);
}

// 0c) Pack [Wrm | Wrs] -> g_Wrt [n=128][k=128] bf16
__global__ __launch_bounds__(128) void wr_pack(const float* __restrict__ Wrm,
                                               const float* __restrict__ Wrs)
{
    int n = blockIdx.x;
    int k = threadIdx.x;
    float v = (n < 64) ? Wrm[k * 64 + n] : Wrs[k * 64 + (n - 64)];
    g_Wrt[n * 128 + k] = __float2bfloat16(v);
}

// 0d) Pack [Wgm | Wgs] -> g_Wgt [n=256][k=64] bf16
__global__ __launch_bounds__(64) void wg_pack(const float* __restrict__ Wgm,
                                              const float* __restrict__ Wgs)
{
    int n = blockIdx.x;
    int k = threadIdx.x;
    float v = (n < 128) ? Wgm[k * 128 + n] : Wgs[k * 128 + (n - 128)];
    g_Wgt[n * 64 + k] = __float2bfloat16(v);
}

// ============================================================================
// 1) Prior rollout (unchanged — passing version)
// ============================================================================
__global__ __launch_bounds__(64) void prior_kernel(
    const float* __restrict__ im, const float* __restrict__ Wfm,
    const float* __restrict__ bfm, const float* __restrict__ Wfs,
    const float* __restrict__ bfs)
{
    __shared__ float sWm[SS * SS];
    __shared__ float sWs[SS * SS];
    __shared__ float m[2][SS];

    const int j = threadIdx.x;
    const int b = blockIdx.x;

    for (int idx = j; idx < SS * SS; idx += 64) {
        sWm[idx] = Wfm[idx];
        sWs[idx] = Wfs[idx];
    }
    const float bm = bfm[j];
    const float bs = bfs[j];
    m[0][j] = im[b * SS + j];
    __syncthreads();

    float* __restrict__ pmb = g_pm    + (size_t)b * TT * SS;
    float* __restrict__ lqb = g_logsq + (size_t)b * TT * SS;
    float* __restrict__ isb = g_i2s2  + (size_t)b * TT * SS;

    int cur = 0;
    for (int t = 0; t < TT; t++) {
        float am0 = bm, am1 = 0.f, as0 = bs, as1 = 0.f;
        #pragma unroll 8
        for (int i = 0; i < SS; i += 2) {
            float mi0 = m[cur][i];
            float mi1 = m[cur][i + 1];
            am0 = fmaf(mi0, sWm[i * SS + j], am0);
            am1 = fmaf(mi1, sWm[(i + 1) * SS + j], am1);
            as0 = fmaf(mi0, sWs[i * SS + j], as0);
            as1 = fmaf(mi1, sWs[(i + 1) * SS + j], as1);
        }
        float am = am0 + am1;
        float sp = softplusf(as0 + as1);

        pmb[t * SS + j] = am;
        lqb[t * SS + j] = logf(sp);
        isb[t * SS + j] = 0.5f / (sp * sp);

        m[cur ^ 1][j] = am;
        __syncthreads();
        cur ^= 1;
    }
}

// ============================================================================
// 2) X = obs @ K_lstm + b_lstm via HMMA (unchanged — passing version)
// ============================================================================
#define XSTR 136
#define XSM_A 0
#define XSM_B (128 * XSTR * 2)
#define XSM_BIAS (2 * 128 * XSTR * 2)
#define XSM_TOT (XSM_BIAS + 128 * 4)

__global__ __launch_bounds__(256, 2) void xgemm_mma(const float* __restrict__ bias)
{
    extern __shared__ unsigned char smraw[];
    __nv_bfloat16* sA = (__nv_bfloat16*)(smraw + XSM_A);
    __nv_bfloat16* sB = (__nv_bfloat16*)(smraw + XSM_B);
    float* sbias = (float*)(smraw + XSM_BIAS);

    const int tid  = threadIdx.x;
    const int lane = tid & 31;
    const int wid  = tid >> 5;
    const int m0 = blockIdx.x * 128;
    const int n0 = blockIdx.y * 128;

    {
        const int r  = tid >> 4;
        const int cc = (tid & 15) * 8;
        #pragma unroll
        for (int i = 0; i < 8; i++) {
            int row = r + i * 16;
            uint4 va = *(const uint4*)(g_Abf + (size_t)(m0 + row) * OO + cc);
            *(uint4*)(sA + row * XSTR + cc) = va;
            uint4 vb = *(const uint4*)(g_Kt + (size_t)(n0 + row) * OO + cc);
            *(uint4*)(sB + row * XSTR + cc) = vb;
        }
    }
    if (tid < 128) sbias[tid] = bias[n0 + tid];
    __syncthreads();

    const int wm = (wid & 3) * 32;
    const int wn = (wid >> 2) * 64;
    const uint32_t sA_u = smem_u32(sA);
    const uint32_t sB_u = smem_u32(sB);

    float acc[2][8][4];
    #pragma unroll
    for (int im = 0; im < 2; im++)
        #pragma unroll
        for (int j = 0; j < 8; j++)
            #pragma unroll
            for (int c = 0; c < 4; c++) acc[im][j][c] = 0.f;

    const int q  = lane >> 3;
    const int r8 = lane & 7;

    #pragma unroll
    for (int kk = 0; kk < 8; kk++) {
        const int k0 = kk * 16;
        uint32_t ra[2][4];
        #pragma unroll
        for (int im = 0; im < 2; im++) {
            int row = wm + im * 16 + (q & 1) * 8 + r8;
            int col = k0 + (q >> 1) * 8;
            uint32_t addr = sA_u + (uint32_t)((row * XSTR + col) * 2);
            asm volatile(
                "ldmatrix.sync.aligned.m8n8.x4.shared.b16 {%0,%1,%2,%3}, [%4];"
                : "=r"(ra[im][0]), "=r"(ra[im][1]), "=r"(ra[im][2]), "=r"(ra[im][3])
                : "r"(addr));
        }
        uint32_t rb[8][2];
        #pragma unroll
        for (int jn = 0; jn < 4; jn++) {
            int row = wn + jn * 16 + (q >> 1) * 8 + r8;
            int col = k0 + (q & 1) * 8;
            uint32_t addr = sB_u + (uint32_t)((row * XSTR + col) * 2);
            asm volatile(
                "ldmatrix.sync.aligned.m8n8.x4.shared.b16 {%0,%1,%2,%3}, [%4];"
                : "=r"(rb[2 * jn][0]), "=r"(rb[2 * jn][1]),
                  "=r"(rb[2 * jn + 1][0]), "=r"(rb[2 * jn + 1][1])
                : "r"(addr));
        }
        #pragma unroll
        for (int im = 0; im < 2; im++)
            #pragma unroll
            for (int j = 0; j < 8; j++) {
                asm volatile(
                    "mma.sync.aligned.m16n8k16.row.col.f32.bf16.bf16.f32 "
                    "{%0,%1,%2,%3}, {%4,%5,%6,%7}, {%8,%9}, {%0,%1,%2,%3};"
                    : "+f"(acc[im][j][0]), "+f"(acc[im][j][1]),
                      "+f"(acc[im][j][2]), "+f"(acc[im][j][3])
                    : "r"(ra[im][0]), "r"(ra[im][1]), "r"(ra[im][2]), "r"(ra[im][3]),
                      "r"(rb[j][0]), "r"(rb[j][1]));
            }
    }

    const int g  = lane >> 2;
    const int t2 = (lane & 3) * 2;
    #pragma unroll
    for (int im = 0; im < 2; im++) {
        #pragma unroll
        for (int j = 0; j < 8; j++) {
            const int col = wn + j * 8 + t2;
            const float bx = sbias[col];
            const float by = sbias[col + 1];
            const int row = m0 + wm + im * 16 + g;
            float2 v0, v1;
            v0.x = acc[im][j][0] + bx; v0.y = acc[im][j][1] + by;
            v1.x = acc[im][j][2] + bx; v1.y = acc[im][j][3] + by;
            *(float2*)(g_X + (size_t)row * GG + n0 + col)       = v0;
            *(float2*)(g_X + (size_t)(row + 8) * GG + n0 + col) = v1;
        }
    }
}

// ============================================================================
// 3) LSTM recurrence via HMMA with register-resident R fragments.
//    32 blocks x 8 batch rows, 256 threads (8 warps). Warp w owns gate cols
//    [64w, 64w+64). R^T fragments live in registers (128 regs/thread).
//    h double-buffered bf16 in smem; x prefetched with cp.async.
// ============================================================================
// smem runtime layout (bytes):
#define LXB0 0                      // xbuf0: [8][516] fp32 = 16512
#define LXB1 16512                  // xbuf1
#define LZB  33024                  // zbuf : [8][516] fp32 = 16512
#define LHB0 49536                  // hbuf0: [16][136] bf16 = 4352
#define LHB1 53888                  // hbuf1
#define LSTM_SMEM_NEW 139264        // prologue R staging: 8 warps * 64*136*2

__global__ __launch_bounds__(256, 1) void lstm_mma()
{
    extern __shared__ unsigned char sm[];
    const uint32_t smb = smem_u32(sm);

    const int tid  = threadIdx.x;
    const int lane = tid & 31;
    const int w    = tid >> 5;           // warp id 0..7
    const int r0   = blockIdx.x * 8;     // batch rows r0..r0+7

    // ---- prologue: stage this warp's R^T slice [64n,128k], ldmatrix to regs ----
    uint32_t rb[8][8][2];
    {
        __nv_bfloat16* ws = (__nv_bfloat16*)(sm + w * 17408);  // 64*136*2
        const __nv_bfloat16* src = g_Rt + (size_t)(w * 64) * HH;
        #pragma unroll
        for (int it = 0; it < 32; it++) {
            int id = lane + it * 32;     // 0..1023
            int row = id >> 4;
            int u = id & 15;
            *(uint4*)(ws + row * 136 + u * 8) = *(const uint4*)(src + row * HH + u * 8);
        }
        __syncwarp();
        const uint32_t ws_u = smem_u32(ws);
        const int q  = lane >> 3;
        const int r8 = lane & 7;
        #pragma unroll
        for (int kk = 0; kk < 8; kk++) {
            #pragma unroll
            for (int jp = 0; jp < 4; jp++) {
                int row = jp * 16 + (q >> 1) * 8 + r8;
                int col = kk * 16 + (q & 1) * 8;
                uint32_t addr = ws_u + (uint32_t)(row * 272 + col * 2);
                asm volatile(
                    "ldmatrix.sync.aligned.m8n8.x4.shared.b16 {%0,%1,%2,%3}, [%4];"
                    : "=r"(rb[kk][2 * jp][0]), "=r"(rb[kk][2 * jp][1]),
                      "=r"(rb[kk][2 * jp + 1][0]), "=r"(rb[kk][2 * jp + 1][1])
                    : "r"(addr));
            }
        }
    }
    __syncthreads();

    // zero h buffers (both, all 16 rows incl. padding)
    for (int i = tid; i < 2176; i += 256) {          // 8704 B / 4
        *(uint32_t*)(sm + LHB0 + i * 4) = 0;
    }

    // prefetch x(t=0) into xbuf0
    {
        #pragma unroll
        for (int i = 0; i < 4; i++) {
            int id = tid + i * 256;                  // 0..1023
            int row = id >> 7;
            int c16 = id & 127;
            const float* src = g_X + ((size_t)(r0 + row) * TT + 0) * GG + c16 * 4;
            uint32_t dst = smb + LXB0 + (uint32_t)(row * 2064 + c16 * 16);
            asm volatile("cp.async.cg.shared.global [%0], [%1], 16;" :: "r"(dst), "l"(src));
        }
        asm volatile("cp.async.commit_group;");
    }
    __syncthreads();

    const int q  = lane >> 3;
    const int r8 = lane & 7;
    const int grow = lane >> 2;          // acc row 0..7
    const int gc2  = (lane & 3) * 2;     // acc col pair base

    // gate-phase constants: warp w handles batch row w, 4 cols per lane
    const int gcol = lane * 4;
    float cst[4] = {0.f, 0.f, 0.f, 0.f};
    __nv_bfloat16* hsg = g_hsb + ((size_t)(r0 + w) * TT) * HH + gcol;

    int cur = 0;
    for (int t = 0; t < TT; t++) {
        const int nxt = cur ^ 1;
        // prefetch x(t+1)
        if (t + 1 < TT) {
            #pragma unroll
            for (int i = 0; i < 4; i++) {
                int id = tid + i * 256;
                int row = id >> 7;
                int c16 = id & 127;
                const float* src = g_X + ((size_t)(r0 + row) * TT + (t + 1)) * GG + c16 * 4;
                uint32_t dst = smb + (nxt ? LXB1 : LXB0) + (uint32_t)(row * 2064 + c16 * 16);
                asm volatile("cp.async.cg.shared.global [%0], [%1], 16;" :: "r"(dst), "l"(src));
            }
        }
        asm volatile("cp.async.commit_group;");
        asm volatile("cp.async.wait_group 1;");   // x(t) ready
        __syncthreads();                          // also covers hbuf[cur] from prev gates

        // A fragments from hbuf[cur]
        uint32_t ra[8][4];
        {
            const uint32_t hb = smb + (cur ? LHB1 : LHB0);
            #pragma unroll
            for (int kk = 0; kk < 8; kk++) {
                int row = (q & 1) * 8 + r8;
                int col = kk * 16 + (q >> 1) * 8;
                uint32_t addr = hb + (uint32_t)(row * 272 + col * 2);
                asm volatile(
                    "ldmatrix.sync.aligned.m8n8.x4.shared.b16 {%0,%1,%2,%3}, [%4];"
                    : "=r"(ra[kk][0]), "=r"(ra[kk][1]), "=r"(ra[kk][2]), "=r"(ra[kk][3])
                    : "r"(addr));
            }
        }

        // acc init from xbuf[cur]: rows 0-7 real, rows 8-15 zero
        float acc[8][4];
        {
            const float* xb = (const float*)(sm + (cur ? LXB1 : LXB0));
            #pragma unroll
            for (int jn = 0; jn < 8; jn++) {
                int col = w * 64 + jn * 8 + gc2;
                float2 v = *(const float2*)(xb + grow * 516 + col);
                acc[jn][0] = v.x; acc[jn][1] = v.y;
                acc[jn][2] = 0.f; acc[jn][3] = 0.f;
            }
        }

        // 64 HMMA
        #pragma unroll
        for (int kk = 0; kk < 8; kk++)
            #pragma unroll
            for (int jn = 0; jn < 8; jn++) {
                asm volatile(
                    "mma.sync.aligned.m16n8k16.row.col.f32.bf16.bf16.f32 "
                    "{%0,%1,%2,%3}, {%4,%5,%6,%7}, {%8,%9}, {%0,%1,%2,%3};"
                    : "+f"(acc[jn][0]), "+f"(acc[jn][1]),
                      "+f"(acc[jn][2]), "+f"(acc[jn][3])
                    : "r"(ra[kk][0]), "r"(ra[kk][1]), "r"(ra[kk][2]), "r"(ra[kk][3]),
                      "r"(rb[kk][jn][0]), "r"(rb[kk][jn][1]));
            }

        // store z (rows 0-7) to zbuf
        {
            float* zb = (float*)(sm + LZB);
            #pragma unroll
            for (int jn = 0; jn < 8; jn++) {
                int col = w * 64 + jn * 8 + gc2;
                *(float2*)(zb + grow * 516 + col) = make_float2(acc[jn][0], acc[jn][1]);
            }
        }
        __syncthreads();

        // gate math: warp w = batch row w; lane handles cols gcol..gcol+3
        {
            const float* zr = (const float*)(sm + LZB) + w * 516;
            float4 zi = *(const float4*)(zr + gcol);
            float4 zf = *(const float4*)(zr + gcol + 128);
            float4 zg = *(const float4*)(zr + gcol + 256);
            float4 zo = *(const float4*)(zr + gcol + 384);

            float h0, h1, h2, h3;
            cst[0] = sigmoid_fast(zf.x) * cst[0] + sigmoid_fast(zi.x) * tanh_fast(zg.x);
            h0 = sigmoid_fast(zo.x) * tanh_fast(cst[0]);
            cst[1] = sigmoid_fast(zf.y) * cst[1] + sigmoid_fast(zi.y) * tanh_fast(zg.y);
            h1 = sigmoid_fast(zo.y) * tanh_fast(cst[1]);
            cst[2] = sigmoid_fast(zf.z) * cst[2] + sigmoid_fast(zi.z) * tanh_fast(zg.z);
            h2 = sigmoid_fast(zo.z) * tanh_fast(cst[2]);
            cst[3] = sigmoid_fast(zf.w) * cst[3] + sigmoid_fast(zi.w) * tanh_fast(zg.w);
            h3 = sigmoid_fast(zo.w) * tanh_fast(cst[3]);

            __nv_bfloat162 p0 = __floats2bfloat162_rn(h0, h1);
            __nv_bfloat162 p1 = __floats2bfloat162_rn(h2, h3);
            // h -> hbuf[nxt] (row w)
            __nv_bfloat16* hb = (__nv_bfloat16*)(sm + (nxt ? LHB1 : LHB0)) + w * 136 + gcol;
            *(__nv_bfloat162*)(hb)     = p0;
            *(__nv_bfloat162*)(hb + 2) = p1;
            // h -> global
            *(__nv_bfloat162*)(hsg + (size_t)t * HH)     = p0;
            *(__nv_bfloat162*)(hsg + (size_t)t * HH + 2) = p1;
        }
        __syncthreads();
        cur = nxt;
    }
}

// ============================================================================
// 4a) G1: P = hs @ [Wrm|Wrs] + [brm|brs]  (unchanged — passing version)
// ============================================================================
__global__ __launch_bounds__(256, 2) void g1_mma(const float* __restrict__ brm,
                                                 const float* __restrict__ brs)
{
    extern __shared__ unsigned char smraw[];
    __nv_bfloat16* sA = (__nv_bfloat16*)(smraw + XSM_A);
    __nv_bfloat16* sB = (__nv_bfloat16*)(smraw + XSM_B);
    float* sbias = (float*)(smraw + XSM_BIAS);

    const int tid  = threadIdx.x;
    const int lane = tid & 31;
    const int wid  = tid >> 5;
    const int m0 = blockIdx.x * 128;

    {
        const int r  = tid >> 4;
        const int cc = (tid & 15) * 8;
        #pragma unroll
        for (int i = 0; i < 8; i++) {
            int row = r + i * 16;
            uint4 va = *(const uint4*)(g_hsb + (size_t)(m0 + row) * HH + cc);
            *(uint4*)(sA + row * XSTR + cc) = va;
            uint4 vb = *(const uint4*)(g_Wrt + (size_t)row * 128 + cc);
            *(uint4*)(sB + row * XSTR + cc) = vb;
        }
    }
    if (tid < 128) sbias[tid] = (tid < 64) ? brm[tid] : brs[tid - 64];
    __syncthreads();

    const int wm = (wid & 3) * 32;
    const int wn = (wid >> 2) * 64;
    const uint32_t sA_u = smem_u32(sA);
    const uint32_t sB_u = smem_u32(sB);

    float acc[2][8][4];
    #pragma unroll
    for (int im = 0; im < 2; im++)
        #pragma unroll
        for (int j = 0; j < 8; j++)
            #pragma unroll
            for (int c = 0; c < 4; c++) acc[im][j][c] = 0.f;

    const int q  = lane >> 3;
    const int r8 = lane & 7;

    #pragma unroll
    for (int kk = 0; kk < 8; kk++) {
        const int k0 = kk * 16;
        uint32_t ra[2][4];
        #pragma unroll
        for (int im = 0; im < 2; im++) {
            int row = wm + im * 16 + (q & 1) * 8 + r8;
            int col = k0 + (q >> 1) * 8;
            uint32_t addr = sA_u + (uint32_t)((row * XSTR + col) * 2);
            asm volatile(
                "ldmatrix.sync.aligned.m8n8.x4.shared.b16 {%0,%1,%2,%3}, [%4];"
                : "=r"(ra[im][0]), "=r"(ra[im][1]), "=r"(ra[im][2]), "=r"(ra[im][3])
                : "r"(addr));
        }
        uint32_t rb[8][2];
        #pragma unroll
        for (int jn = 0; jn < 4; jn++) {
            int row = wn + jn * 16 + (q >> 1) * 8 + r8;
            int col = k0 + (q & 1) * 8;
            uint32_t addr = sB_u + (uint32_t)((row * XSTR + col) * 2);
            asm volatile(
                "ldmatrix.sync.aligned.m8n8.x4.shared.b16 {%0,%1,%2,%3}, [%4];"
                : "=r"(rb[2 * jn][0]), "=r"(rb[2 * jn][1]),
                  "=r"(rb[2 * jn + 1][0]), "=r"(rb[2 * jn + 1][1])
                : "r"(addr));
        }
        #pragma unroll
        for (int im = 0; im < 2; im++)
            #pragma unroll
            for (int j = 0; j < 8; j++) {
                asm volatile(
                    "mma.sync.aligned.m16n8k16.row.col.f32.bf16.bf16.f32 "
                    "{%0,%1,%2,%3}, {%4,%5,%6,%7}, {%8,%9}, {%0,%1,%2,%3};"
                    : "+f"(acc[im][j][0]), "+f"(acc[im][j][1]),
                      "+f"(acc[im][j][2]), "+f"(acc[im][j][3])
                    : "r"(ra[im][0]), "r"(ra[im][1]), "r"(ra[im][2]), "r"(ra[im][3]),
                      "r"(rb[j][0]), "r"(rb[j][1]));
            }
    }

    const int g  = lane >> 2;
    const int t2 = (lane & 3) * 2;
    #pragma unroll
    for (int im = 0; im < 2; im++) {
        #pragma unroll
        for (int j = 0; j < 8; j++) {
            const int col = wn + j * 8 + t2;
            const float bx = sbias[col];
            const float by = sbias[col + 1];
            const int row = m0 + wm + im * 16 + g;
            float2 v0, v1;
            v0.x = acc[im][j][0] + bx; v0.y = acc[im][j][1] + by;
            v1.x = acc[im][j][2] + bx; v1.y = acc[im][j][3] + by;
            *(float2*)(g_P + (size_t)row * 128 + col)       = v0;
            *(float2*)(g_P + (size_t)(row + 8) * 128 + col) = v1;
            if (wn == 0) {
                *(__nv_bfloat162*)(g_pmb + (size_t)row * 64 + col)
                    = __floats2bfloat162_rn(v0.x, v0.y);
                *(__nv_bfloat162*)(g_pmb + (size_t)(row + 8) * 64 + col)
                    = __floats2bfloat162_rn(v1.x, v1.y);
            }
        }
    }
}

// ============================================================================
// 4b) G2: Q = post_mean @ [Wgm|Wgs] + [bgm|bgs]  (unchanged — passing version)
// ============================================================================
#define YSTR 72
#define YSM_A 0
#define YSM_B (128 * YSTR * 2)
#define YSM_BIAS (2 * 128 * YSTR * 2)
#define YSM_TOT (YSM_BIAS + 128 * 4)

__global__ __launch_bounds__(256, 2) void g2_mma(const float* __restrict__ bgm,
                                                 const float* __restrict__ bgs)
{
    extern __shared__ unsigned char smraw[];
    __nv_bfloat16* sA = (__nv_bfloat16*)(smraw + YSM_A);
    __nv_bfloat16* sB = (__nv_bfloat16*)(smraw + YSM_B);
    float* sbias = (float*)(smraw + YSM_BIAS);

    const int tid  = threadIdx.x;
    const int lane = tid & 31;
    const int wid  = tid >> 5;
    const int m0 = blockIdx.x * 128;
    const int ny = blockIdx.y;

    {
        const int r  = tid >> 3;
        const int cc = (tid & 7) * 8;
        #pragma unroll
        for (int i = 0; i < 4; i++) {
            int row = r + i * 32;
            uint4 va = *(const uint4*)(g_pmb + (size_t)(m0 + row) * 64 + cc);
            *(uint4*)(sA + row * YSTR + cc) = va;
            uint4 vb = *(const uint4*)(g_Wgt + (size_t)(ny * 128 + row) * 64 + cc);
            *(uint4*)(sB + row * YSTR + cc) = vb;
        }
    }
    if (tid < 128) sbias[tid] = ny ? bgs[tid] : bgm[tid];
    __syncthreads();

    const int wm = (wid & 3) * 32;
    const int wn = (wid >> 2) * 64;
    const uint32_t sA_u = smem_u32(sA);
    const uint32_t sB_u = smem_u32(sB);

    float acc[2][8][4];
    #pragma unroll
    for (int im = 0; im < 2; im++)
        #pragma unroll
        for (int j = 0; j < 8; j++)
            #pragma unroll
            for (int c = 0; c < 4; c++) acc[im][j][c] = 0.f;

    const int q  = lane >> 3;
    const int r8 = lane & 7;

    #pragma unroll
    for (int kk = 0; kk < 4; kk++) {
        const int k0 = kk * 16;
        uint32_t ra[2][4];
        #pragma unroll
        for (int im = 0; im < 2; im++) {
            int row = wm + im * 16 + (q & 1) * 8 + r8;
            int col = k0 + (q >> 1) * 8;
            uint32_t addr = sA_u + (uint32_t)((row * YSTR + col) * 2);
            asm volatile(
                "ldmatrix.sync.aligned.m8n8.x4.shared.b16 {%0,%1,%2,%3}, [%4];"
                : "=r"(ra[im][0]), "=r"(ra[im][1]), "=r"(ra[im][2]), "=r"(ra[im][3])
                : "r"(addr));
        }
        uint32_t rb[8][2];
        #pragma unroll
        for (int jn = 0; jn < 4; jn++) {
            int row = wn + jn * 16 + (q >> 1) * 8 + r8;
            int col = k0 + (q & 1) * 8;
            uint32_t addr = sB_u + (uint32_t)((row * YSTR + col) * 2);
            asm volatile(
                "ldmatrix.sync.aligned.m8n8.x4.shared.b16 {%0,%1,%2,%3}, [%4];"
                : "=r"(rb[2 * jn][0]), "=r"(rb[2 * jn][1]),
                  "=r"(rb[2 * jn + 1][0]), "=r"(rb[2 * jn + 1][1])
                : "r"(addr));
        }
        #pragma unroll
        for (int im = 0; im < 2; im++)
            #pragma unroll
            for (int j = 0; j < 8; j++) {
                asm volatile(
                    "mma.sync.aligned.m16n8k16.row.col.f32.bf16.bf16.f32 "
                    "{%0,%1,%2,%3}, {%4,%5,%6,%7}, {%8,%9}, {%0,%1,%2,%3};"
                    : "+f"(acc[im][j][0]), "+f"(acc[im][j][1]),
                      "+f"(acc[im][j][2]), "+f"(acc[im][j][3])
                    : "r"(ra[im][0]), "r"(ra[im][1]), "r"(ra[im][2]), "r"(ra[im][3]),
                      "r"(rb[j][0]), "r"(rb[j][1]));
            }
    }

    const int g  = lane >> 2;
    const int t2 = (lane & 3) * 2;
    #pragma unroll
    for (int im = 0; im < 2; im++) {
        #pragma unroll
        for (int j = 0; j < 8; j++) {
            const int col = wn + j * 8 + t2;
            const float bx = sbias[col];
            const float by = sbias[col + 1];
            const int row = m0 + wm + im * 16 + g;
            float2 v0, v1;
            v0.x = acc[im][j][0] + bx; v0.y = acc[im][j][1] + by;
            v1.x = acc[im][j][2] + bx; v1.y = acc[im][j][3] + by;
            *(float2*)(g_Q + (size_t)row * 256 + ny * 128 + col)       = v0;
            *(float2*)(g_Q + (size_t)(row + 8) * 256 + ny * 128 + col) = v1;
        }
    }
}

// ============================================================================
// 4c) Elementwise KL + reconstruction (unchanged — passing version)
// ============================================================================
__global__ __launch_bounds__(256) void lossew_kernel(const float* __restrict__ obs)
{
    __shared__ float sred[512];
    const int tid = threadIdx.x;

    float klp = 0.f, rec = 0.f;

    {
        size_t base = (size_t)blockIdx.x * 4096 + tid;
        #pragma unroll 4
        for (int k = 0; k < 16; k++) {
            size_t idx = base + (size_t)k * 256;
            size_t row = idx >> 6;
            int s = (int)(idx & 63);
            float pm  = g_P[row * 128 + s];
            float pre = g_P[row * 128 + 64 + s];
            float sp  = softplus_fast(pre);
            float dm  = pm - g_pm[idx];
            klp += g_logsq[idx] - __logf(sp)
                 + (sp * sp + dm * dm) * g_i2s2[idx] - 0.5f;
        }
    }
    {
        size_t base = (size_t)blockIdx.x * 8192 + tid;
        #pragma unroll 4
        for (int k = 0; k < 32; k++) {
            size_t idx = base + (size_t)k * 256;
            size_t row = idx >> 7;
            int o = (int)(idx & 127);
            float om  = g_Q[row * 256 + o];
            float osp = g_Q[row * 256 + 128 + o];
            float os  = softplus_fast(osp);
            float d   = (obs[idx] - om) * __frcp_rn(os);
            rec += 0.5f * d * d + __logf(os) + 0.91893853320467274f;
        }
    }

    sred[tid]       = klp;
    sred[256 + tid] = rec;
    __syncthreads();
    #pragma unroll
    for (int st = 128; st > 0; st >>= 1) {
        if (tid < st) {
            sred[tid]       += sred[tid + st];
            sred[256 + tid] += sred[256 + tid + st];
        }
        __syncthreads();
    }
    if (tid == 0) {
        g_part[blockIdx.x * 2]     = sred[0];
        g_part[blockIdx.x * 2 + 1] = sred[256];
    }
}

// ============================================================================
// 5) Final deterministic reduce
// ============================================================================
__global__ __launch_bounds__(256) void reduce_kernel(float* __restrict__ out)
{
    __shared__ double sk[256];
    __shared__ double sr[256];
    const int tid = threadIdx.x;
    double k = 0.0, r = 0.0;
    for (int i = tid; i < LOSS_BLOCKS; i += 256) {
        k += (double)g_part[2 * i];
        r += (double)g_part[2 * i + 1];
    }
    sk[tid] = k; sr[tid] = r;
    __syncthreads();
    #pragma unroll
    for (int st = 128; st > 0; st >>= 1) {
        if (tid < st) { sk[tid] += sk[tid + st]; sr[tid] += sr[tid + st]; }
        __syncthreads();
    }
    if (tid == 0)
        out[0] = (float)(sk[0] / ((double)BB * (double)TT) + sr[0] / (double)BB);
}

// ============================================================================
// launch
// ============================================================================
extern "C" void kernel_launch(void* const* d_in, const int* in_sizes, int n_in,
                              void* d_out, int out_size)
{
    const float* obs = (const float*)d_in[0];
    const float* im  = (const float*)d_in[1];
    const float* Wfm = (const float*)d_in[3];
    const float* bfm = (const float*)d_in[4];
    const float* Wfs = (const float*)d_in[5];
    const float* bfs = (const float*)d_in[6];
    const float* Wgm = (const float*)d_in[7];
    const float* bgm = (const float*)d_in[8];
    const float* Wgs = (const float*)d_in[9];
    const float* bgs = (const float*)d_in[10];
    const float* K   = (const float*)d_in[11];
    const float* R   = (const float*)d_in[12];
    const float* bl  = (const float*)d_in[13];
    const float* Wrm = (const float*)d_in[14];
    const float* brm = (const float*)d_in[15];
    const float* Wrs = (const float*)d_in[16];
    const float* brs = (const float*)d_in[17];

    cudaFuncSetAttribute(lstm_mma,  cudaFuncAttributeMaxDynamicSharedMemorySize, LSTM_SMEM_NEW);
    cudaFuncSetAttribute(xgemm_mma, cudaFuncAttributeMaxDynamicSharedMemorySize, XSM_TOT);
    cudaFuncSetAttribute(g1_mma,    cudaFuncAttributeMaxDynamicSharedMemorySize, XSM_TOT);
    cudaFuncSetAttribute(g2_mma,    cudaFuncAttributeMaxDynamicSharedMemorySize, YSM_TOT);

    conv_kernel<<<(MT * OO / 4) / 256, 256>>>(obs);
    kt_kernel<<<GG, 128>>>(K);
    rt_pack<<<GG, 128>>>(R);
    wr_pack<<<128, 128>>>(Wrm, Wrs);
    wg_pack<<<256, 64>>>(Wgm, Wgs);
    prior_kernel<<<BB, 64>>>(im, Wfm, bfm, Wfs, bfs);
    xgemm_mma<<<dim3(MT / 128, GG / 128), 256, XSM_TOT>>>(bl);
    lstm_mma<<<BB / 8, 256, LSTM_SMEM_NEW>>>();
    g1_mma<<<MT / 128, 256, XSM_TOT>>>(brm, brs);
    g2_mma<<<dim3(MT / 128, 2), 256, YSM_TOT>>>(bgm, bgs);
    lossew_kernel<<<LOSS_BLOCKS, 256>>>(obs);
    reduce_kernel<<<1, 256>>>((float*)d_out);
}